// round 13
// baseline (speedup 1.0000x reference)
#include <cuda_runtime.h>
#include <cuda_fp16.h>
#include <cstdint>

static constexpr int   kN  = 50000;
static constexpr int   kE  = 600000;
static constexpr int   kC  = 128;
static constexpr int   kG  = 256;
static constexpr float kPI = 3.14159265358979323846f;

// ---------------- scratch (device globals; no allocation allowed) ----------------
__device__ int    g_deg[kN];
__device__ int    g_rowptr[kN + 1];
__device__ int    g_fill[kN];
__device__ int    g_csr_src[kE];
__device__ int    g_csr_dst[kE];
__device__ int    g_csr_eid[kE];
__device__ int    g_bsums[512];
__device__ int    g_gcnt[kG];
__device__ int    g_gptr[kG + 1];
__device__ float  g_loop[kN * kC];
__device__ float  g_xl[kN * kC];
__device__ float  g_xr[kN * kC];
__device__ float  g_h[kN * kC];
__device__ float  g_ase[kE];
__device__ float  g_asf[kN];
__device__ float  g_bns[4 * kC];              // layer1: [0,256), layer2: [256,512)
__device__ __half g_eah[(size_t)kE * kC];     // fp16 edge_attr at CSR positions
// B weights fp16 hi/lo packed per mma fragment: [mat(8)][kk(8)][ntile(16)][lane(32)] uint4
__device__ uint4  g_BF[8 * 4096];

// ---------------- small utility kernels ----------------
__global__ void zero3(int* deg, int* fill, int* gcnt, float* bns, int n) {
    int i = blockIdx.x * blockDim.x + threadIdx.x;
    if (i < n) { deg[i] = 0; fill[i] = 0; }
    if (i < kG) gcnt[i] = 0;
    if (i < 4 * kC) bns[i] = 0.f;
}
__global__ void hist_kernel(const int* __restrict__ keys, int* __restrict__ cnt, int n) {
    int i = blockIdx.x * blockDim.x + threadIdx.x;
    if (i < n) atomicAdd(&cnt[keys[i]], 1);
}
__global__ void scan_block(const int* __restrict__ in, int* __restrict__ out,
                           int* __restrict__ bsums, int n) {
    __shared__ int sm[512];
    int tid = threadIdx.x;
    int i = blockIdx.x * 512 + tid;
    int v = (i < n) ? in[i] : 0;
    sm[tid] = v;
    __syncthreads();
#pragma unroll
    for (int off = 1; off < 512; off <<= 1) {
        int t = (tid >= off) ? sm[tid - off] : 0;
        __syncthreads();
        sm[tid] += t;
        __syncthreads();
    }
    if (i < n) out[i] = sm[tid] - v;
    if (tid == 511) bsums[blockIdx.x] = sm[511];
}
__global__ void scan_sums(int* bsums, int nb) {
    __shared__ int sm[512];
    int tid = threadIdx.x;
    int v = (tid < nb) ? bsums[tid] : 0;
    sm[tid] = v;
    __syncthreads();
#pragma unroll
    for (int off = 1; off < 512; off <<= 1) {
        int t = (tid >= off) ? sm[tid - off] : 0;
        __syncthreads();
        sm[tid] += t;
        __syncthreads();
    }
    if (tid < nb) bsums[tid] = sm[tid] - v;
}
__global__ void scan_add(int* out, const int* __restrict__ bsums, int n, int total, int* tail) {
    int i = blockIdx.x * 512 + threadIdx.x;
    if (i < n) out[i] += bsums[blockIdx.x];
    if (blockIdx.x == 0 && threadIdx.x == 0) *tail = total;
}
__global__ void gscan(const int* __restrict__ cnt, int* __restrict__ gptr) {
    __shared__ int sm[256];
    int t = threadIdx.x;
    sm[t] = cnt[t];
    __syncthreads();
#pragma unroll
    for (int off = 1; off < 256; off <<= 1) {
        int u = (t >= off) ? sm[t - off] : 0;
        __syncthreads();
        sm[t] += u;
        __syncthreads();
    }
    if (t == 0) gptr[0] = 0;
    gptr[t + 1] = sm[t];
}
__global__ void scatter_kernel(const int* __restrict__ src, const int* __restrict__ dst,
                               const int* __restrict__ rowptr, int* __restrict__ fill,
                               int* __restrict__ csr_src, int* __restrict__ csr_dst,
                               int* __restrict__ csr_eid, int n) {
    int i = blockIdx.x * blockDim.x + threadIdx.x;
    if (i >= n) return;
    int d = dst[i];
    int pos = rowptr[d] + atomicAdd(&fill[d], 1);
    csr_src[pos] = src[i];
    csr_dst[pos] = d;
    csr_eid[pos] = i;
}

// loop_attr from fp16 edge rows at CSR positions (sequential per node)
__global__ void __launch_bounds__(256) loopattr_kernel(const __half* __restrict__ eah,
                                                       const int* __restrict__ rowptr,
                                                       float* __restrict__ loopb) {
    int w = (blockIdx.x * blockDim.x + threadIdx.x) >> 5;
    int lane = threadIdx.x & 31;
    if (w >= kN) return;
    int b0 = rowptr[w], b1 = rowptr[w + 1];
    float4 acc = make_float4(0.f, 0.f, 0.f, 0.f);
    const uint2* e2 = (const uint2*)eah;
    for (int j = b0; j < b1; j++) {
        uint2 v = e2[(size_t)j * 32 + lane];
        __half2 h0 = *reinterpret_cast<__half2*>(&v.x);
        __half2 h1 = *reinterpret_cast<__half2*>(&v.y);
        float2 f0 = __half22float2(h0), f1 = __half22float2(h1);
        acc.x += f0.x; acc.y += f0.y; acc.z += f1.x; acc.w += f1.y;
    }
    int dg = b1 - b0;
    float inv = 1.f / (float)(dg > 0 ? dg : 1);
    acc.x *= inv; acc.y *= inv; acc.z *= inv; acc.w *= inv;
    ((float4*)loopb)[(size_t)w * 32 + lane] = acc;
}

__device__ __forceinline__ uint32_t pack2h(float a, float b) {
    __half2 t = __floats2half2_rn(a, b);
    return *reinterpret_cast<uint32_t*>(&t);
}

// ---------------- weight prep: fp16 hi/lo split into mma FRAGMENT order ----------------
__global__ void prep_B(const float* W0, const float* W1, const float* W2, const float* W3,
                       const float* W4, const float* W5, const float* W6, const float* W7,
                       uint4* BF) {
    const float* Ws[8] = {W0, W1, W2, W3, W4, W5, W6, W7};
    const float* W = Ws[blockIdx.x];
    uint4* bf = BF + blockIdx.x * 4096;
    for (int idx = threadIdx.x; idx < 4096; idx += blockDim.x) {
        int lane = idx & 31, nt = (idx >> 5) & 15, kk = idx >> 9;
        int n = nt * 8 + (lane >> 2);
        int k = kk * 16 + (lane & 3) * 2;
        float v00 = W[(size_t)k * 128 + n];
        float v01 = W[(size_t)(k + 1) * 128 + n];
        float v10 = W[(size_t)(k + 8) * 128 + n];
        float v11 = W[(size_t)(k + 9) * 128 + n];
        __half h00 = __float2half_rn(v00), h01 = __float2half_rn(v01);
        __half h10 = __float2half_rn(v10), h11 = __float2half_rn(v11);
        bf[idx] = make_uint4(pack2h(__half2float(h00), __half2float(h01)),
                             pack2h(__half2float(h10), __half2float(h11)),
                             pack2h(v00 - __half2float(h00), v01 - __half2float(h01)),
                             pack2h(v10 - __half2float(h10), v11 - __half2float(h11)));
    }
}

// ============ fp16 2-term tensor-core GEMM (mma.sync), 512 thr, 2 CTA/SM ============
static constexpr int SMS   = 136;
static constexpr int SM_A  = 0;                        // 128 x SMS fp16 = 34816 B
static constexpr int SM_FB = 34816;                    // 128 x CSTR f32 = 67584 B
static constexpr int SM_EX = SM_FB + 67584;            // 256 floats
static constexpr int SM_RA = SM_EX + 1024;             // 128 floats
static constexpr int SM_BN = SM_RA + 512;              // 256 floats (sc, sh)
static constexpr int SM_TOT = SM_BN + 1024;            // 104960
static constexpr int CSTR  = 132;

__device__ __forceinline__ uint32_t smem_u32(const void* p) {
    uint32_t a;
    asm("{ .reg .u64 t; cvta.to.shared.u64 t, %1; cvt.u32.u64 %0, t; }" : "=r"(a) : "l"(p));
    return a;
}
__device__ __forceinline__ void ldsm4(uint32_t* r, uint32_t addr) {
    asm volatile("ldmatrix.sync.aligned.m8n8.x4.shared.b16 {%0,%1,%2,%3}, [%4];"
                 : "=r"(r[0]), "=r"(r[1]), "=r"(r[2]), "=r"(r[3]) : "r"(addr));
}
__device__ __forceinline__ void mma16816(float* c, const uint32_t* a, uint32_t b0, uint32_t b1) {
    asm volatile("mma.sync.aligned.m16n8k16.row.col.f32.f16.f16.f32 "
                 "{%0,%1,%2,%3}, {%4,%5,%6,%7}, {%8,%9}, {%0,%1,%2,%3};"
                 : "+f"(c[0]), "+f"(c[1]), "+f"(c[2]), "+f"(c[3])
                 : "r"(a[0]), "r"(a[1]), "r"(a[2]), "r"(a[3]), "r"(b0), "r"(b1));
}

// MODE: 0 node(+bias) [DUAL optional],
//       2 edge score l1 (gather ea via eid, exports eah),
//       3 self score (s=d=row),
//       5 edge score l2 (A = eah fp16 direct),
//       6 fused gate: pass0 tanh(A@B+extra)->A-smem, pass1 @B2+extra2 -> out
// BN: A input is raw h; apply tanh(h*sc + sh) per channel in the A-stage.
template <int MODE, bool DUAL, bool BN>
__global__ void __launch_bounds__(512, 2) mma_gemm(const float* __restrict__ A,
                                                   const __half* __restrict__ Ah,
                                                   const uint4* __restrict__ BF,
                                                   const uint4* __restrict__ B2F,
                                                   const float* __restrict__ extra,
                                                   const float* __restrict__ extra2,
                                                   const float* __restrict__ xl,
                                                   const float* __restrict__ xr,
                                                   const int* __restrict__ srcI,
                                                   const int* __restrict__ dstI,
                                                   const int* __restrict__ eid,
                                                   __half* __restrict__ eah_out,
                                                   const float* __restrict__ bn_st,
                                                   const float* __restrict__ bn_g,
                                                   const float* __restrict__ bn_b,
                                                   float* __restrict__ out,
                                                   float* __restrict__ out2, int M) {
    extern __shared__ char smem[];
    const uint32_t sb = smem_u32(smem);
    const int tid = threadIdx.x, w = tid >> 5, lane = tid & 31;
    const int row0 = blockIdx.x * 128;
    float* fbuf = (float*)(smem + SM_FB);
    float* exS = (float*)(smem + SM_EX);
    float* rowacc = (float*)(smem + SM_RA);
    float* bnS = (float*)(smem + SM_BN);

    // ---- A stage ----
    if (MODE == 5) {
        uint4 hv[4];
#pragma unroll
        for (int u = 0; u < 4; u++) {
            int i = tid + u * 512;
            int r = i >> 4, c16 = i & 15;
            int grow = row0 + r;
            hv[u] = (grow < M) ? ((const uint4*)Ah)[(size_t)grow * 16 + c16]
                               : make_uint4(0u, 0u, 0u, 0u);
        }
        if (tid < 128) exS[tid] = extra[tid];
#pragma unroll
        for (int u = 0; u < 4; u++) {
            int i = tid + u * 512;
            int r = i >> 4, c16 = i & 15;
            *(uint4*)(smem + SM_A + (uint32_t)(r * SMS + c16 * 8) * 2u) = hv[u];
        }
    } else {
        float4 av[8];
#pragma unroll
        for (int u = 0; u < 8; u++) {
            int i = tid + u * 512;
            int r = i >> 5, c4 = (i & 31) << 2;
            int grow = row0 + r;
            av[u] = make_float4(0.f, 0.f, 0.f, 0.f);
            if (grow < M) {
                size_t arow = (MODE == 2) ? (size_t)eid[grow] : (size_t)grow;
                av[u] = *(const float4*)(A + arow * 128 + c4);
            }
        }
        if (tid < 128) exS[tid] = extra[tid];
        if ((DUAL || MODE == 6) && tid >= 128 && tid < 256) exS[tid] = extra2[tid - 128];
        if (BN) {
            if (tid < 128) {
                float mean = bn_st[tid] * (1.f / (float)kN);
                float var = bn_st[128 + tid] * (1.f / (float)kN) - mean * mean;
                float sc = rsqrtf(var + 1e-5f) * bn_g[tid];
                bnS[tid] = sc;
                bnS[128 + tid] = bn_b[tid] - mean * sc;
            }
            __syncthreads();
        }
#pragma unroll
        for (int u = 0; u < 8; u++) {
            int i = tid + u * 512;
            int r = i >> 5, c4 = (i & 31) << 2;
            float4 v = av[u];
            if (BN) {
                v.x = tanhf(fmaf(v.x, bnS[c4 + 0], bnS[128 + c4 + 0]));
                v.y = tanhf(fmaf(v.y, bnS[c4 + 1], bnS[128 + c4 + 1]));
                v.z = tanhf(fmaf(v.z, bnS[c4 + 2], bnS[128 + c4 + 2]));
                v.w = tanhf(fmaf(v.w, bnS[c4 + 3], bnS[128 + c4 + 3]));
            }
            uint2 pk = make_uint2(pack2h(v.x, v.y), pack2h(v.z, v.w));
            *(uint2*)(smem + SM_A + (uint32_t)(r * SMS + c4) * 2u) = pk;
            if (MODE == 2) {
                int grow = row0 + r;
                if (grow < M) ((uint2*)eah_out)[(size_t)grow * 32 + (c4 >> 2)] = pk;
            }
        }
    }
    __syncthreads();

    const int m_base = (w & 3) * 32;
    const int nt0 = (w >> 2) * 4;
    const int n_base = nt0 * 8;
    const int lr = lane & 15, lc = lane >> 4;
    const int tg = lane >> 2, tq = lane & 3;
    const int NPASS = (DUAL || MODE == 6) ? 2 : 1;

#pragma unroll
    for (int pass = 0; pass < NPASS; pass++) {
        const uint4* Bp = pass ? B2F : BF;
        float acc[2][4][4];
#pragma unroll
        for (int mi = 0; mi < 2; mi++)
#pragma unroll
            for (int ni = 0; ni < 4; ni++)
#pragma unroll
                for (int q = 0; q < 4; q++) acc[mi][ni][q] = 0.f;

#pragma unroll
        for (int kk = 0; kk < 8; kk++) {
            int k0 = kk * 16;
            uint4 b[4];
            const uint4* bp = Bp + ((kk * 16 + nt0) * 32 + lane);
#pragma unroll
            for (int ni = 0; ni < 4; ni++) b[ni] = bp[ni * 32];
#pragma unroll
            for (int mi = 0; mi < 2; mi++) {
                uint32_t a[4];
                ldsm4(a, sb + SM_A + (uint32_t)((m_base + mi * 16 + lr) * SMS + k0 + lc * 8) * 2u);
#pragma unroll
                for (int ni = 0; ni < 4; ni++) mma16816(acc[mi][ni], a, b[ni].x, b[ni].y);
#pragma unroll
                for (int ni = 0; ni < 4; ni++) mma16816(acc[mi][ni], a, b[ni].z, b[ni].w);
            }
        }
        __syncthreads();   // mainloop reads done

        if (MODE == 6 && pass == 0) {
#pragma unroll
            for (int mi = 0; mi < 2; mi++) {
                int rlo = m_base + mi * 16 + tg;
#pragma unroll
                for (int ni = 0; ni < 4; ni++) {
                    int c0 = n_base + ni * 8 + 2 * tq;
                    float v0 = tanhf(acc[mi][ni][0] + exS[c0]);
                    float v1 = tanhf(acc[mi][ni][1] + exS[c0 + 1]);
                    float v2 = tanhf(acc[mi][ni][2] + exS[c0]);
                    float v3 = tanhf(acc[mi][ni][3] + exS[c0 + 1]);
                    *(uint32_t*)(smem + SM_A + (uint32_t)(rlo * SMS + c0) * 2u) = pack2h(v0, v1);
                    *(uint32_t*)(smem + SM_A + (uint32_t)((rlo + 8) * SMS + c0) * 2u) = pack2h(v2, v3);
                }
            }
            __syncthreads();
            continue;
        }

        if (MODE == 0 || MODE == 6) {
            const float* ex = exS + (pass ? 128 : 0);
#pragma unroll
            for (int mi = 0; mi < 2; mi++) {
                int rlo = m_base + mi * 16 + tg;
#pragma unroll
                for (int ni = 0; ni < 4; ni++) {
                    int c0 = n_base + ni * 8 + 2 * tq;
                    float v0 = acc[mi][ni][0] + ex[c0];
                    float v1 = acc[mi][ni][1] + ex[c0 + 1];
                    float v2 = acc[mi][ni][2] + ex[c0];
                    float v3 = acc[mi][ni][3] + ex[c0 + 1];
                    *(float2*)(fbuf + rlo * CSTR + c0) = make_float2(v0, v1);
                    *(float2*)(fbuf + (rlo + 8) * CSTR + c0) = make_float2(v2, v3);
                }
            }
            __syncthreads();
            float* o = (DUAL && pass) ? out2 : out;
#pragma unroll
            for (int u = 0; u < 8; u++) {
                int i = tid + u * 512;
                int r = i >> 5, c4 = (i & 31) << 2;
                if (row0 + r < M)
                    *(float4*)(o + (size_t)(row0 + r) * 128 + c4) = *(float4*)(fbuf + r * CSTR + c4);
            }
            if (DUAL && pass == 0) __syncthreads();
        } else {
            if (tid < 128) rowacc[tid] = 0.f;
#pragma unroll
            for (int half = 0; half < 2; half++) {
                int su[4], du[4];
#pragma unroll
                for (int u = 0; u < 4; u++) {
                    int i = tid + (half * 4 + u) * 512;
                    int r = i >> 5;
                    int grow = row0 + r;
                    if (grow >= M) grow = M - 1;
                    su[u] = (MODE == 3) ? grow : srcI[grow];
                    du[u] = (MODE == 3) ? grow : dstI[grow];
                }
                float4 ga[4], gb[4];
#pragma unroll
                for (int u = 0; u < 4; u++) {
                    int i = tid + (half * 4 + u) * 512;
                    int c = i & 31;
                    ga[u] = ((const float4*)xl)[(size_t)su[u] * 32 + c];
                    gb[u] = ((const float4*)xr)[(size_t)du[u] * 32 + c];
                }
#pragma unroll
                for (int u = 0; u < 4; u++) {
                    int i = tid + (half * 4 + u) * 512;
                    int r = i >> 5, c = i & 31;
                    *(float4*)(fbuf + r * CSTR + c * 4) =
                        make_float4(ga[u].x + gb[u].x, ga[u].y + gb[u].y,
                                    ga[u].z + gb[u].z, ga[u].w + gb[u].w);
                }
            }
            __syncthreads();
#pragma unroll
            for (int mi = 0; mi < 2; mi++) {
                int rlo = m_base + mi * 16 + tg;
                int rhi = rlo + 8;
                float p0 = 0.f, p1 = 0.f;
#pragma unroll
                for (int ni = 0; ni < 4; ni++) {
                    int c0 = n_base + ni * 8 + 2 * tq;
                    float e0 = exS[c0], e1 = exS[c0 + 1];
                    float2 flo = *(const float2*)(fbuf + rlo * CSTR + c0);
                    float2 fhi = *(const float2*)(fbuf + rhi * CSTR + c0);
                    float v;
                    v = acc[mi][ni][0] + flo.x;  v = (v > 0.f) ? v : 0.2f * v;  p0 = fmaf(v, e0, p0);
                    v = acc[mi][ni][1] + flo.y;  v = (v > 0.f) ? v : 0.2f * v;  p0 = fmaf(v, e1, p0);
                    v = acc[mi][ni][2] + fhi.x;  v = (v > 0.f) ? v : 0.2f * v;  p1 = fmaf(v, e0, p1);
                    v = acc[mi][ni][3] + fhi.y;  v = (v > 0.f) ? v : 0.2f * v;  p1 = fmaf(v, e1, p1);
                }
                atomicAdd(&rowacc[rlo], p0);
                atomicAdd(&rowacc[rhi], p1);
            }
            __syncthreads();
            if (tid < 128 && row0 + tid < M) out[row0 + tid] = rowacc[tid];
        }
    }
}

// ------- softmax + aggregation (warp per node, CSR) + fused BN partial stats -------
__global__ void __launch_bounds__(256) aggregate_kernel(const int* __restrict__ rowptr,
                                                        const int* __restrict__ csr_src,
                                                        const float* __restrict__ ae,
                                                        const float* __restrict__ as,
                                                        const float* __restrict__ xl,
                                                        const float* __restrict__ bo,
                                                        float* __restrict__ h,
                                                        float* __restrict__ bns_out) {
    __shared__ float s1[8 * 128];
    __shared__ float s2[8 * 128];
    int tid = threadIdx.x, w = tid >> 5, lane = tid & 31;
    int n = (blockIdx.x * blockDim.x + tid) >> 5;
    float4 acc = make_float4(0.f, 0.f, 0.f, 0.f);
    if (n < kN) {
        int b0 = rowptr[n], b1 = rowptr[n + 1];
        float aself = as[n];
        float am = aself;
        for (int j = b0 + lane; j < b1; j += 32) am = fmaxf(am, ae[j]);
#pragma unroll
        for (int off = 16; off; off >>= 1) am = fmaxf(am, __shfl_xor_sync(0xffffffffu, am, off));
        float den = 0.f;
        for (int j = b0 + lane; j < b1; j += 32) den += __expf(ae[j] - am);
#pragma unroll
        for (int off = 16; off; off >>= 1) den += __shfl_xor_sync(0xffffffffu, den, off);
        float wself = __expf(aself - am);
        den += wself;
        float inv = 1.f / den;

        const float4* xl4 = (const float4*)xl;
        int j = b0;
        // 4-wide unrolled gather: batch indices, then 4 independent row loads (MLP=4)
        for (; j + 3 < b1; j += 4) {
            float w0 = __expf(ae[j + 0] - am);
            float w1 = __expf(ae[j + 1] - am);
            float w2 = __expf(ae[j + 2] - am);
            float w3 = __expf(ae[j + 3] - am);
            int i0 = csr_src[j + 0], i1 = csr_src[j + 1];
            int i2 = csr_src[j + 2], i3 = csr_src[j + 3];
            float4 v0 = xl4[(size_t)i0 * 32 + lane];
            float4 v1 = xl4[(size_t)i1 * 32 + lane];
            float4 v2 = xl4[(size_t)i2 * 32 + lane];
            float4 v3 = xl4[(size_t)i3 * 32 + lane];
            acc.x = fmaf(w0, v0.x, fmaf(w1, v1.x, fmaf(w2, v2.x, fmaf(w3, v3.x, acc.x))));
            acc.y = fmaf(w0, v0.y, fmaf(w1, v1.y, fmaf(w2, v2.y, fmaf(w3, v3.y, acc.y))));
            acc.z = fmaf(w0, v0.z, fmaf(w1, v1.z, fmaf(w2, v2.z, fmaf(w3, v3.z, acc.z))));
            acc.w = fmaf(w0, v0.w, fmaf(w1, v1.w, fmaf(w2, v2.w, fmaf(w3, v3.w, acc.w))));
        }
        for (; j < b1; j++) {
            float w0 = __expf(ae[j] - am);
            float4 v0 = xl4[(size_t)csr_src[j] * 32 + lane];
            acc.x = fmaf(w0, v0.x, acc.x); acc.y = fmaf(w0, v0.y, acc.y);
            acc.z = fmaf(w0, v0.z, acc.z); acc.w = fmaf(w0, v0.w, acc.w);
        }
        {
            float4 v = xl4[(size_t)n * 32 + lane];
            acc.x = fmaf(wself, v.x, acc.x); acc.y = fmaf(wself, v.y, acc.y);
            acc.z = fmaf(wself, v.z, acc.z); acc.w = fmaf(wself, v.w, acc.w);
        }
        float4 b = ((const float4*)bo)[lane];
        acc.x = fmaf(acc.x, inv, b.x); acc.y = fmaf(acc.y, inv, b.y);
        acc.z = fmaf(acc.z, inv, b.z); acc.w = fmaf(acc.w, inv, b.w);
        ((float4*)h)[(size_t)n * 32 + lane] = acc;
    }
    ((float4*)s1)[w * 32 + lane] = acc;
    ((float4*)s2)[w * 32 + lane] =
        make_float4(acc.x * acc.x, acc.y * acc.y, acc.z * acc.z, acc.w * acc.w);
    __syncthreads();
    if (tid < 128) {
        float a = 0.f, b = 0.f;
#pragma unroll
        for (int ww = 0; ww < 8; ww++) { a += s1[ww * 128 + tid]; b += s2[ww * 128 + tid]; }
        atomicAdd(&bns_out[tid], a);
        atomicAdd(&bns_out[128 + tid], b);
    }
}

// --------- attentional pooling + final linear fused (block per graph, 256 thr) ---------
__global__ void __launch_bounds__(256) pool_final(const float* __restrict__ gate,
                                                  const float* __restrict__ h,
                                                  const int* __restrict__ gptr,
                                                  const float* __restrict__ bns2,
                                                  const float* __restrict__ g2,
                                                  const float* __restrict__ be2,
                                                  const float* __restrict__ Wf,
                                                  const float* __restrict__ bf,
                                                  float* __restrict__ out) {
    int g = blockIdx.x, tid = threadIdx.x;
    int c = tid & 127, half = tid >> 7;
    __shared__ float sm_m[256], sm_d[256], sm_a[256];
    __shared__ float ps[128];
    int s0 = gptr[g], s1 = gptr[g + 1];
    float mean = bns2[c] * (1.f / (float)kN);
    float var = bns2[128 + c] * (1.f / (float)kN) - mean * mean;
    float sc = rsqrtf(var + 1e-5f) * g2[c];
    float sh = be2[c] - mean * sc;

    float m = -1e30f, den = 0.f, acc = 0.f;
    for (int n = s0 + half; n < s1; n += 2) {
        float gv = gate[(size_t)n * 128 + c];
        float hv = tanhf(fmaf(h[(size_t)n * 128 + c], sc, sh));
        if (gv > m) {
            float corr = __expf(m - gv);
            den *= corr;
            acc *= corr;
            m = gv;
        }
        float e = __expf(gv - m);
        den += e;
        acc = fmaf(e, hv, acc);
    }
    sm_m[tid] = m; sm_d[tid] = den; sm_a[tid] = acc;
    __syncthreads();
    if (tid < 128) {
        float m1 = sm_m[tid + 128], d1 = sm_d[tid + 128], a1 = sm_a[tid + 128];
        float pv = 0.f;
        if (s0 < s1) {
            float M = fmaxf(m, m1);
            float w0 = __expf(m - M), w1 = __expf(m1 - M);
            float D = den * w0 + d1 * w1;
            pv = (acc * w0 + a1 * w1) / D;
        }
        ps[c] = pv;
    }
    __syncthreads();
    if (tid < 128) {
        float a = bf[c];
#pragma unroll 8
        for (int k = 0; k < 128; k++) a = fmaf(ps[k], Wf[(size_t)k * 128 + c], a);
        float o = tanhf(a);
        if (c < 64) out[(size_t)g * 64 + c] = o * kPI;
        else        out[(size_t)kG * 64 + (size_t)g * 64 + (c - 64)] = (o + 1.f) * kPI;
    }
}

// ---------------- launch ----------------
extern "C" void kernel_launch(void* const* d_in, const int* in_sizes, int n_in,
                              void* d_out, int out_size) {
    (void)in_sizes; (void)n_in; (void)out_size;
    const float* x    = (const float*)d_in[0];
    const int*   ei   = (const int*)  d_in[1];
    const float* ea   = (const float*)d_in[2];
    const int*   bat  = (const int*)  d_in[3];
    const float* Wl1  = (const float*)d_in[4];
    const float* bl1  = (const float*)d_in[5];
    const float* Wr1  = (const float*)d_in[6];
    const float* br1  = (const float*)d_in[7];
    const float* We1  = (const float*)d_in[8];
    const float* att1 = (const float*)d_in[9];
    const float* bo1  = (const float*)d_in[10];
    const float* Wl2  = (const float*)d_in[11];
    const float* bl2  = (const float*)d_in[12];
    const float* Wr2  = (const float*)d_in[13];
    const float* br2  = (const float*)d_in[14];
    const float* We2  = (const float*)d_in[15];
    const float* att2 = (const float*)d_in[16];
    const float* bo2  = (const float*)d_in[17];
    const float* g1   = (const float*)d_in[18];
    const float* be1  = (const float*)d_in[19];
    const float* g2   = (const float*)d_in[20];
    const float* be2  = (const float*)d_in[21];
    const float* Ag1  = (const float*)d_in[22];
    const float* bg1  = (const float*)d_in[23];
    const float* Ag2  = (const float*)d_in[24];
    const float* bg2  = (const float*)d_in[25];
    const float* Wf   = (const float*)d_in[26];
    const float* bf   = (const float*)d_in[27];
    float* out = (float*)d_out;

    int *deg, *rowptr, *fill, *csr_src, *csr_dst, *csr_eid, *bsums, *gcnt, *gptr;
    float *loopb, *xl, *xr, *h, *ase, *asf, *bns;
    __half* eah;
    uint4* BF;
    cudaGetSymbolAddress((void**)&deg,     g_deg);
    cudaGetSymbolAddress((void**)&rowptr,  g_rowptr);
    cudaGetSymbolAddress((void**)&fill,    g_fill);
    cudaGetSymbolAddress((void**)&csr_src, g_csr_src);
    cudaGetSymbolAddress((void**)&csr_dst, g_csr_dst);
    cudaGetSymbolAddress((void**)&csr_eid, g_csr_eid);
    cudaGetSymbolAddress((void**)&bsums,   g_bsums);
    cudaGetSymbolAddress((void**)&gcnt,    g_gcnt);
    cudaGetSymbolAddress((void**)&gptr,    g_gptr);
    cudaGetSymbolAddress((void**)&loopb,   g_loop);
    cudaGetSymbolAddress((void**)&xl,      g_xl);
    cudaGetSymbolAddress((void**)&xr,      g_xr);
    cudaGetSymbolAddress((void**)&h,       g_h);
    cudaGetSymbolAddress((void**)&ase,     g_ase);
    cudaGetSymbolAddress((void**)&asf,     g_asf);
    cudaGetSymbolAddress((void**)&bns,     g_bns);
    cudaGetSymbolAddress((void**)&eah,     g_eah);
    cudaGetSymbolAddress((void**)&BF,      g_BF);

    cudaFuncSetAttribute(mma_gemm<0, true,  false>, cudaFuncAttributeMaxDynamicSharedMemorySize, SM_TOT);
    cudaFuncSetAttribute(mma_gemm<0, true,  true>,  cudaFuncAttributeMaxDynamicSharedMemorySize, SM_TOT);
    cudaFuncSetAttribute(mma_gemm<2, false, false>, cudaFuncAttributeMaxDynamicSharedMemorySize, SM_TOT);
    cudaFuncSetAttribute(mma_gemm<3, false, false>, cudaFuncAttributeMaxDynamicSharedMemorySize, SM_TOT);
    cudaFuncSetAttribute(mma_gemm<5, false, false>, cudaFuncAttributeMaxDynamicSharedMemorySize, SM_TOT);
    cudaFuncSetAttribute(mma_gemm<6, false, true>,  cudaFuncAttributeMaxDynamicSharedMemorySize, SM_TOT);

    const int* srcp = ei;
    const int* dstp = ei + kE;
    const int gN = (kN + 127) / 128;
    const int gE = (kE + 127) / 128;
    const int nb = (kN + 511) / 512;

    prep_B<<<8, 256>>>(Wl1, Wr1, We1, Wl2, Wr2, We2, Ag1, Ag2, BF);                                   // 0
    zero3<<<(kN + 255) / 256, 256>>>(deg, fill, gcnt, bns, kN);                                       // 1
    hist_kernel<<<(kE + 255) / 256, 256>>>(dstp, deg, kE);                                            // 2
    mma_gemm<0, true, false><<<gN, 512, SM_TOT>>>(x, nullptr, BF + 0 * 4096, BF + 1 * 4096, bl1, br1,
                                                  nullptr, nullptr, nullptr, nullptr, nullptr, nullptr,
                                                  nullptr, nullptr, nullptr, xl, xr, kN);             // 3 <- profile
    hist_kernel<<<(kN + 255) / 256, 256>>>(bat, gcnt, kN);
    scan_block<<<nb, 512>>>(deg, rowptr, bsums, kN);
    scan_sums<<<1, 512>>>(bsums, nb);
    scan_add<<<nb, 512>>>(rowptr, bsums, kN, kE, rowptr + kN);
    gscan<<<1, 256>>>(gcnt, gptr);
    scatter_kernel<<<(kE + 255) / 256, 256>>>(srcp, dstp, rowptr, fill, csr_src, csr_dst, csr_eid, kE);

    // ---- layer 1 ----
    mma_gemm<2, false, false><<<gE, 512, SM_TOT>>>(ea, nullptr, BF + 2 * 4096, nullptr, att1, nullptr,
                                                   xl, xr, csr_src, csr_dst, csr_eid, eah,
                                                   nullptr, nullptr, nullptr, ase, nullptr, kE);
    loopattr_kernel<<<(kN + 7) / 8, 256>>>(eah, rowptr, loopb);
    mma_gemm<3, false, false><<<gN, 512, SM_TOT>>>(loopb, nullptr, BF + 2 * 4096, nullptr, att1, nullptr,
                                                   xl, xr, nullptr, nullptr, nullptr, nullptr,
                                                   nullptr, nullptr, nullptr, asf, nullptr, kN);
    aggregate_kernel<<<(kN + 7) / 8, 256>>>(rowptr, csr_src, ase, asf, xl, bo1, h, bns);

    // ---- layer 2 (BN-1 applied inside the A stage of the dual node GEMM) ----
    mma_gemm<0, true, true><<<gN, 512, SM_TOT>>>(h, nullptr, BF + 3 * 4096, BF + 4 * 4096, bl2, br2,
                                                 nullptr, nullptr, nullptr, nullptr, nullptr, nullptr,
                                                 bns, g1, be1, xl, xr, kN);
    mma_gemm<3, false, false><<<gN, 512, SM_TOT>>>(loopb, nullptr, BF + 5 * 4096, nullptr, att2, nullptr,
                                                   xl, xr, nullptr, nullptr, nullptr, nullptr,
                                                   nullptr, nullptr, nullptr, asf, nullptr, kN);
    mma_gemm<5, false, false><<<gE, 512, SM_TOT>>>(nullptr, eah, BF + 5 * 4096, nullptr, att2, nullptr,
                                                   xl, xr, csr_src, csr_dst, nullptr, nullptr,
                                                   nullptr, nullptr, nullptr, ase, nullptr, kE);
    aggregate_kernel<<<(kN + 7) / 8, 256>>>(rowptr, csr_src, ase, asf, xl, bo2, h, bns + 256);

    // ---- fused gate (BN-2 in A stage) + fused pool/final ----
    mma_gemm<6, false, true><<<gN, 512, SM_TOT>>>(h, nullptr, BF + 6 * 4096, BF + 7 * 4096, bg1, bg2,
                                                  nullptr, nullptr, nullptr, nullptr, nullptr, nullptr,
                                                  bns + 256, g2, be2, xr, nullptr, kN);
    pool_final<<<kG, 256>>>(xr, h, gptr, bns + 256, g2, be2, Wf, bf, out);
}

// round 16
// speedup vs baseline: 1.1221x; 1.1221x over previous
#include <cuda_runtime.h>
#include <cuda_fp16.h>
#include <cstdint>

static constexpr int   kN  = 50000;
static constexpr int   kE  = 600000;
static constexpr int   kC  = 128;
static constexpr int   kG  = 256;
static constexpr float kPI = 3.14159265358979323846f;

// ---------------- scratch (device globals; no allocation allowed) ----------------
__device__ int    g_deg[kN];
__device__ int    g_rowptr[kN + 1];
__device__ int    g_fill[kN];
__device__ int    g_csr_src[kE];
__device__ int    g_csr_dst[kE];
__device__ int    g_csr_eid[kE];
__device__ int    g_bsums[512];
__device__ int    g_gcnt[kG];
__device__ int    g_gptr[kG + 1];
__device__ float  g_loop[kN * kC];
__device__ float  g_xl[kN * kC];
__device__ float  g_xr[kN * kC];
__device__ float  g_h[kN * kC];
__device__ float  g_ase[kE];
__device__ float  g_asf[kN];
__device__ float  g_bns[4 * kC];              // layer1: [0,256), layer2: [256,512)
__device__ __half g_eah[(size_t)kE * kC];     // fp16 edge_attr at CSR positions
// B weights fp16 hi/lo packed per mma fragment: [mat(8)][kk(8)][ntile(16)][lane(32)] uint4
__device__ uint4  g_BF[8 * 4096];

// ---------------- small utility kernels ----------------
__global__ void zero3(int* deg, int* fill, int* gcnt, float* bns, int n) {
    int i = blockIdx.x * blockDim.x + threadIdx.x;
    if (i < n) { deg[i] = 0; fill[i] = 0; }
    if (i < kG) gcnt[i] = 0;
    if (i < 4 * kC) bns[i] = 0.f;
}
__global__ void hist_kernel(const int* __restrict__ keys, int* __restrict__ cnt, int n) {
    int i = blockIdx.x * blockDim.x + threadIdx.x;
    if (i < n) atomicAdd(&cnt[keys[i]], 1);
}
__global__ void scan_block(const int* __restrict__ in, int* __restrict__ out,
                           int* __restrict__ bsums, int n) {
    __shared__ int sm[512];
    int tid = threadIdx.x;
    int i = blockIdx.x * 512 + tid;
    int v = (i < n) ? in[i] : 0;
    sm[tid] = v;
    __syncthreads();
#pragma unroll
    for (int off = 1; off < 512; off <<= 1) {
        int t = (tid >= off) ? sm[tid - off] : 0;
        __syncthreads();
        sm[tid] += t;
        __syncthreads();
    }
    if (i < n) out[i] = sm[tid] - v;
    if (tid == 511) bsums[blockIdx.x] = sm[511];
}
__global__ void scan_sums(int* bsums, int nb) {
    __shared__ int sm[512];
    int tid = threadIdx.x;
    int v = (tid < nb) ? bsums[tid] : 0;
    sm[tid] = v;
    __syncthreads();
#pragma unroll
    for (int off = 1; off < 512; off <<= 1) {
        int t = (tid >= off) ? sm[tid - off] : 0;
        __syncthreads();
        sm[tid] += t;
        __syncthreads();
    }
    if (tid < nb) bsums[tid] = sm[tid] - v;
}
__global__ void scan_add(int* out, const int* __restrict__ bsums, int n, int total, int* tail) {
    int i = blockIdx.x * 512 + threadIdx.x;
    if (i < n) out[i] += bsums[blockIdx.x];
    if (blockIdx.x == 0 && threadIdx.x == 0) *tail = total;
}
__global__ void gscan(const int* __restrict__ cnt, int* __restrict__ gptr) {
    __shared__ int sm[256];
    int t = threadIdx.x;
    sm[t] = cnt[t];
    __syncthreads();
#pragma unroll
    for (int off = 1; off < 256; off <<= 1) {
        int u = (t >= off) ? sm[t - off] : 0;
        __syncthreads();
        sm[t] += u;
        __syncthreads();
    }
    if (t == 0) gptr[0] = 0;
    gptr[t + 1] = sm[t];
}
__global__ void scatter_kernel(const int* __restrict__ src, const int* __restrict__ dst,
                               const int* __restrict__ rowptr, int* __restrict__ fill,
                               int* __restrict__ csr_src, int* __restrict__ csr_dst,
                               int* __restrict__ csr_eid, int n) {
    int i = blockIdx.x * blockDim.x + threadIdx.x;
    if (i >= n) return;
    int d = dst[i];
    int pos = rowptr[d] + atomicAdd(&fill[d], 1);
    csr_src[pos] = src[i];
    csr_dst[pos] = d;
    csr_eid[pos] = i;
}

// loop_attr from fp16 edge rows at CSR positions (sequential per node)
__global__ void __launch_bounds__(256) loopattr_kernel(const __half* __restrict__ eah,
                                                       const int* __restrict__ rowptr,
                                                       float* __restrict__ loopb) {
    int w = (blockIdx.x * blockDim.x + threadIdx.x) >> 5;
    int lane = threadIdx.x & 31;
    if (w >= kN) return;
    int b0 = rowptr[w], b1 = rowptr[w + 1];
    float4 acc = make_float4(0.f, 0.f, 0.f, 0.f);
    const uint2* e2 = (const uint2*)eah;
    for (int j = b0; j < b1; j++) {
        uint2 v = e2[(size_t)j * 32 + lane];
        __half2 h0 = *reinterpret_cast<__half2*>(&v.x);
        __half2 h1 = *reinterpret_cast<__half2*>(&v.y);
        float2 f0 = __half22float2(h0), f1 = __half22float2(h1);
        acc.x += f0.x; acc.y += f0.y; acc.z += f1.x; acc.w += f1.y;
    }
    int dg = b1 - b0;
    float inv = 1.f / (float)(dg > 0 ? dg : 1);
    acc.x *= inv; acc.y *= inv; acc.z *= inv; acc.w *= inv;
    ((float4*)loopb)[(size_t)w * 32 + lane] = acc;
}

__device__ __forceinline__ uint32_t pack2h(float a, float b) {
    __half2 t = __floats2half2_rn(a, b);
    return *reinterpret_cast<uint32_t*>(&t);
}

// ---------------- weight prep: fp16 hi/lo split into mma FRAGMENT order ----------------
__global__ void prep_B(const float* W0, const float* W1, const float* W2, const float* W3,
                       const float* W4, const float* W5, const float* W6, const float* W7,
                       uint4* BF) {
    const float* Ws[8] = {W0, W1, W2, W3, W4, W5, W6, W7};
    const float* W = Ws[blockIdx.x];
    uint4* bf = BF + blockIdx.x * 4096;
    for (int idx = threadIdx.x; idx < 4096; idx += blockDim.x) {
        int lane = idx & 31, nt = (idx >> 5) & 15, kk = idx >> 9;
        int n = nt * 8 + (lane >> 2);
        int k = kk * 16 + (lane & 3) * 2;
        float v00 = W[(size_t)k * 128 + n];
        float v01 = W[(size_t)(k + 1) * 128 + n];
        float v10 = W[(size_t)(k + 8) * 128 + n];
        float v11 = W[(size_t)(k + 9) * 128 + n];
        __half h00 = __float2half_rn(v00), h01 = __float2half_rn(v01);
        __half h10 = __float2half_rn(v10), h11 = __float2half_rn(v11);
        bf[idx] = make_uint4(pack2h(__half2float(h00), __half2float(h01)),
                             pack2h(__half2float(h10), __half2float(h11)),
                             pack2h(v00 - __half2float(h00), v01 - __half2float(h01)),
                             pack2h(v10 - __half2float(h10), v11 - __half2float(h11)));
    }
}

// ============ fp16 2-term tensor-core GEMM (mma.sync), 512 thr, 2 CTA/SM ============
static constexpr int SMS   = 136;
static constexpr int SM_A  = 0;                        // 128 x SMS fp16 = 34816 B
static constexpr int SM_FB = 34816;                    // 128 x CSTR f32 = 67584 B
static constexpr int SM_EX = SM_FB + 67584;            // 256 floats
static constexpr int SM_RA = SM_EX + 1024;             // 128 floats
static constexpr int SM_BN = SM_RA + 512;              // 256 floats (sc, sh)
static constexpr int SM_TOT = SM_BN + 1024;            // 104960
static constexpr int CSTR  = 132;

__device__ __forceinline__ uint32_t smem_u32(const void* p) {
    uint32_t a;
    asm("{ .reg .u64 t; cvta.to.shared.u64 t, %1; cvt.u32.u64 %0, t; }" : "=r"(a) : "l"(p));
    return a;
}
__device__ __forceinline__ void ldsm4(uint32_t* r, uint32_t addr) {
    asm volatile("ldmatrix.sync.aligned.m8n8.x4.shared.b16 {%0,%1,%2,%3}, [%4];"
                 : "=r"(r[0]), "=r"(r[1]), "=r"(r[2]), "=r"(r[3]) : "r"(addr));
}
__device__ __forceinline__ void mma16816(float* c, const uint32_t* a, uint32_t b0, uint32_t b1) {
    asm volatile("mma.sync.aligned.m16n8k16.row.col.f32.f16.f16.f32 "
                 "{%0,%1,%2,%3}, {%4,%5,%6,%7}, {%8,%9}, {%0,%1,%2,%3};"
                 : "+f"(c[0]), "+f"(c[1]), "+f"(c[2]), "+f"(c[3])
                 : "r"(a[0]), "r"(a[1]), "r"(a[2]), "r"(a[3]), "r"(b0), "r"(b1));
}

// MODE: 0 node(+bias) [DUAL optional],
//       2 edge score l1 (gather ea via eid, exports eah),
//       3 self score (s=d=row),
//       5 edge score l2 (A = eah fp16 direct),
//       6 fused gate: pass0 tanh(A@B+extra)->A-smem, pass1 @B2+extra2 -> out
// BN: A input is raw h; apply tanh(h*sc + sh) per channel in the A-stage.
template <int MODE, bool DUAL, bool BN>
__global__ void __launch_bounds__(512, 2) mma_gemm(const float* __restrict__ A,
                                                   const __half* __restrict__ Ah,
                                                   const uint4* __restrict__ BF,
                                                   const uint4* __restrict__ B2F,
                                                   const float* __restrict__ extra,
                                                   const float* __restrict__ extra2,
                                                   const float* __restrict__ xl,
                                                   const float* __restrict__ xr,
                                                   const int* __restrict__ srcI,
                                                   const int* __restrict__ dstI,
                                                   const int* __restrict__ eid,
                                                   __half* __restrict__ eah_out,
                                                   const float* __restrict__ bn_st,
                                                   const float* __restrict__ bn_g,
                                                   const float* __restrict__ bn_b,
                                                   float* __restrict__ out,
                                                   float* __restrict__ out2, int M) {
    extern __shared__ char smem[];
    const uint32_t sb = smem_u32(smem);
    const int tid = threadIdx.x, w = tid >> 5, lane = tid & 31;
    const int row0 = blockIdx.x * 128;
    float* fbuf = (float*)(smem + SM_FB);
    float* exS = (float*)(smem + SM_EX);
    float* rowacc = (float*)(smem + SM_RA);
    float* bnS = (float*)(smem + SM_BN);

    // ---- A stage ----
    if (MODE == 5) {
        uint2 hv[8];
#pragma unroll
        for (int u = 0; u < 8; u++) {
            int i = tid + u * 512;
            int r = i >> 5, c8 = i & 31;
            int grow = row0 + r;
            hv[u] = (grow < M) ? ((const uint2*)Ah)[(size_t)grow * 32 + c8]
                               : make_uint2(0u, 0u);
        }
        if (tid < 128) exS[tid] = extra[tid];
#pragma unroll
        for (int u = 0; u < 8; u++) {
            int i = tid + u * 512;
            int r = i >> 5, c8 = i & 31;
            *(uint2*)(smem + SM_A + (uint32_t)(r * SMS + c8 * 4) * 2u) = hv[u];
        }
    } else {
        float4 av[8];
#pragma unroll
        for (int u = 0; u < 8; u++) {
            int i = tid + u * 512;
            int r = i >> 5, c4 = (i & 31) << 2;
            int grow = row0 + r;
            av[u] = make_float4(0.f, 0.f, 0.f, 0.f);
            if (grow < M) {
                size_t arow = (MODE == 2) ? (size_t)eid[grow] : (size_t)grow;
                av[u] = *(const float4*)(A + arow * 128 + c4);
            }
        }
        if (tid < 128) exS[tid] = extra[tid];
        if ((DUAL || MODE == 6) && tid >= 128 && tid < 256) exS[tid] = extra2[tid - 128];
        if (BN) {
            if (tid < 128) {
                float mean = bn_st[tid] * (1.f / (float)kN);
                float var = bn_st[128 + tid] * (1.f / (float)kN) - mean * mean;
                float sc = rsqrtf(var + 1e-5f) * bn_g[tid];
                bnS[tid] = sc;
                bnS[128 + tid] = bn_b[tid] - mean * sc;
            }
            __syncthreads();
        }
#pragma unroll
        for (int u = 0; u < 8; u++) {
            int i = tid + u * 512;
            int r = i >> 5, c4 = (i & 31) << 2;
            float4 v = av[u];
            if (BN) {
                v.x = tanhf(fmaf(v.x, bnS[c4 + 0], bnS[128 + c4 + 0]));
                v.y = tanhf(fmaf(v.y, bnS[c4 + 1], bnS[128 + c4 + 1]));
                v.z = tanhf(fmaf(v.z, bnS[c4 + 2], bnS[128 + c4 + 2]));
                v.w = tanhf(fmaf(v.w, bnS[c4 + 3], bnS[128 + c4 + 3]));
            }
            uint2 pk = make_uint2(pack2h(v.x, v.y), pack2h(v.z, v.w));
            *(uint2*)(smem + SM_A + (uint32_t)(r * SMS + c4) * 2u) = pk;
            if (MODE == 2) {
                int grow = row0 + r;
                if (grow < M) ((uint2*)eah_out)[(size_t)grow * 32 + (c4 >> 2)] = pk;
            }
        }
    }
    __syncthreads();

    const int m_base = (w & 3) * 32;
    const int nt0 = (w >> 2) * 4;
    const int n_base = nt0 * 8;
    const int lr = lane & 15, lc = lane >> 4;
    const int tg = lane >> 2, tq = lane & 3;
    const int NPASS = (DUAL || MODE == 6) ? 2 : 1;

#pragma unroll
    for (int pass = 0; pass < NPASS; pass++) {
        const uint4* Bp = pass ? B2F : BF;
        float acc[2][4][4];
#pragma unroll
        for (int mi = 0; mi < 2; mi++)
#pragma unroll
            for (int ni = 0; ni < 4; ni++)
#pragma unroll
                for (int q = 0; q < 4; q++) acc[mi][ni][q] = 0.f;

#pragma unroll
        for (int kk = 0; kk < 8; kk++) {
            int k0 = kk * 16;
            uint4 b[4];
            const uint4* bp = Bp + ((kk * 16 + nt0) * 32 + lane);
#pragma unroll
            for (int ni = 0; ni < 4; ni++) b[ni] = bp[ni * 32];
#pragma unroll
            for (int mi = 0; mi < 2; mi++) {
                uint32_t a[4];
                ldsm4(a, sb + SM_A + (uint32_t)((m_base + mi * 16 + lr) * SMS + k0 + lc * 8) * 2u);
#pragma unroll
                for (int ni = 0; ni < 4; ni++) mma16816(acc[mi][ni], a, b[ni].x, b[ni].y);
#pragma unroll
                for (int ni = 0; ni < 4; ni++) mma16816(acc[mi][ni], a, b[ni].z, b[ni].w);
            }
        }
        __syncthreads();   // mainloop reads done

        if (MODE == 6 && pass == 0) {
#pragma unroll
            for (int mi = 0; mi < 2; mi++) {
                int rlo = m_base + mi * 16 + tg;
#pragma unroll
                for (int ni = 0; ni < 4; ni++) {
                    int c0 = n_base + ni * 8 + 2 * tq;
                    float v0 = tanhf(acc[mi][ni][0] + exS[c0]);
                    float v1 = tanhf(acc[mi][ni][1] + exS[c0 + 1]);
                    float v2 = tanhf(acc[mi][ni][2] + exS[c0]);
                    float v3 = tanhf(acc[mi][ni][3] + exS[c0 + 1]);
                    *(uint32_t*)(smem + SM_A + (uint32_t)(rlo * SMS + c0) * 2u) = pack2h(v0, v1);
                    *(uint32_t*)(smem + SM_A + (uint32_t)((rlo + 8) * SMS + c0) * 2u) = pack2h(v2, v3);
                }
            }
            __syncthreads();
            continue;
        }

        if (MODE == 0 || MODE == 6) {
            const float* ex = exS + (pass ? 128 : 0);
#pragma unroll
            for (int mi = 0; mi < 2; mi++) {
                int rlo = m_base + mi * 16 + tg;
#pragma unroll
                for (int ni = 0; ni < 4; ni++) {
                    int c0 = n_base + ni * 8 + 2 * tq;
                    float v0 = acc[mi][ni][0] + ex[c0];
                    float v1 = acc[mi][ni][1] + ex[c0 + 1];
                    float v2 = acc[mi][ni][2] + ex[c0];
                    float v3 = acc[mi][ni][3] + ex[c0 + 1];
                    *(float2*)(fbuf + rlo * CSTR + c0) = make_float2(v0, v1);
                    *(float2*)(fbuf + (rlo + 8) * CSTR + c0) = make_float2(v2, v3);
                }
            }
            __syncthreads();
            float* o = (DUAL && pass) ? out2 : out;
#pragma unroll
            for (int u = 0; u < 8; u++) {
                int i = tid + u * 512;
                int r = i >> 5, c4 = (i & 31) << 2;
                if (row0 + r < M)
                    *(float4*)(o + (size_t)(row0 + r) * 128 + c4) = *(float4*)(fbuf + r * CSTR + c4);
            }
            if (DUAL && pass == 0) __syncthreads();
        } else {
            if (tid < 128) rowacc[tid] = 0.f;
#pragma unroll
            for (int half = 0; half < 2; half++) {
                int su[4], du[4];
#pragma unroll
                for (int u = 0; u < 4; u++) {
                    int i = tid + (half * 4 + u) * 512;
                    int r = i >> 5;
                    int grow = row0 + r;
                    if (grow >= M) grow = M - 1;
                    su[u] = (MODE == 3) ? grow : srcI[grow];
                    du[u] = (MODE == 3) ? grow : dstI[grow];
                }
                float4 ga[4], gb[4];
#pragma unroll
                for (int u = 0; u < 4; u++) {
                    int i = tid + (half * 4 + u) * 512;
                    int c = i & 31;
                    ga[u] = ((const float4*)xl)[(size_t)su[u] * 32 + c];
                    gb[u] = ((const float4*)xr)[(size_t)du[u] * 32 + c];
                }
#pragma unroll
                for (int u = 0; u < 4; u++) {
                    int i = tid + (half * 4 + u) * 512;
                    int r = i >> 5, c = i & 31;
                    *(float4*)(fbuf + r * CSTR + c * 4) =
                        make_float4(ga[u].x + gb[u].x, ga[u].y + gb[u].y,
                                    ga[u].z + gb[u].z, ga[u].w + gb[u].w);
                }
            }
            __syncthreads();
#pragma unroll
            for (int mi = 0; mi < 2; mi++) {
                int rlo = m_base + mi * 16 + tg;
                int rhi = rlo + 8;
                float p0 = 0.f, p1 = 0.f;
#pragma unroll
                for (int ni = 0; ni < 4; ni++) {
                    int c0 = n_base + ni * 8 + 2 * tq;
                    float e0 = exS[c0], e1 = exS[c0 + 1];
                    float2 flo = *(const float2*)(fbuf + rlo * CSTR + c0);
                    float2 fhi = *(const float2*)(fbuf + rhi * CSTR + c0);
                    float v;
                    v = acc[mi][ni][0] + flo.x;  v = (v > 0.f) ? v : 0.2f * v;  p0 = fmaf(v, e0, p0);
                    v = acc[mi][ni][1] + flo.y;  v = (v > 0.f) ? v : 0.2f * v;  p0 = fmaf(v, e1, p0);
                    v = acc[mi][ni][2] + fhi.x;  v = (v > 0.f) ? v : 0.2f * v;  p1 = fmaf(v, e0, p1);
                    v = acc[mi][ni][3] + fhi.y;  v = (v > 0.f) ? v : 0.2f * v;  p1 = fmaf(v, e1, p1);
                }
                atomicAdd(&rowacc[rlo], p0);
                atomicAdd(&rowacc[rhi], p1);
            }
            __syncthreads();
            if (tid < 128 && row0 + tid < M) out[row0 + tid] = rowacc[tid];
        }
    }
}

// ------- softmax + aggregation (warp per node, CSR) + fused BN partial stats -------
__global__ void __launch_bounds__(256) aggregate_kernel(const int* __restrict__ rowptr,
                                                        const int* __restrict__ csr_src,
                                                        const float* __restrict__ ae,
                                                        const float* __restrict__ as,
                                                        const float* __restrict__ xl,
                                                        const float* __restrict__ bo,
                                                        float* __restrict__ h,
                                                        float* __restrict__ bns_out) {
    __shared__ float s1[8 * 128];
    __shared__ float s2[8 * 128];
    int tid = threadIdx.x, w = tid >> 5, lane = tid & 31;
    int n = (blockIdx.x * blockDim.x + tid) >> 5;
    float4 acc = make_float4(0.f, 0.f, 0.f, 0.f);
    if (n < kN) {
        int b0 = rowptr[n], b1 = rowptr[n + 1];
        float aself = as[n];
        float am = aself;
        for (int j = b0 + lane; j < b1; j += 32) am = fmaxf(am, ae[j]);
#pragma unroll
        for (int off = 16; off; off >>= 1) am = fmaxf(am, __shfl_xor_sync(0xffffffffu, am, off));
        float den = 0.f;
        for (int j = b0 + lane; j < b1; j += 32) den += __expf(ae[j] - am);
#pragma unroll
        for (int off = 16; off; off >>= 1) den += __shfl_xor_sync(0xffffffffu, den, off);
        float wself = __expf(aself - am);
        den += wself;
        float inv = 1.f / den;

        const float4* xl4 = (const float4*)xl;
        int j = b0;
        for (; j + 1 < b1; j += 2) {
            float w0 = __expf(ae[j] - am);
            float w1 = __expf(ae[j + 1] - am);
            int s0i = csr_src[j], s1i = csr_src[j + 1];
            float4 v0 = xl4[(size_t)s0i * 32 + lane];
            float4 v1 = xl4[(size_t)s1i * 32 + lane];
            acc.x = fmaf(w0, v0.x, fmaf(w1, v1.x, acc.x));
            acc.y = fmaf(w0, v0.y, fmaf(w1, v1.y, acc.y));
            acc.z = fmaf(w0, v0.z, fmaf(w1, v1.z, acc.z));
            acc.w = fmaf(w0, v0.w, fmaf(w1, v1.w, acc.w));
        }
        if (j < b1) {
            float w0 = __expf(ae[j] - am);
            float4 v0 = xl4[(size_t)csr_src[j] * 32 + lane];
            acc.x = fmaf(w0, v0.x, acc.x); acc.y = fmaf(w0, v0.y, acc.y);
            acc.z = fmaf(w0, v0.z, acc.z); acc.w = fmaf(w0, v0.w, acc.w);
        }
        {
            float4 v = xl4[(size_t)n * 32 + lane];
            acc.x = fmaf(wself, v.x, acc.x); acc.y = fmaf(wself, v.y, acc.y);
            acc.z = fmaf(wself, v.z, acc.z); acc.w = fmaf(wself, v.w, acc.w);
        }
        float4 b = ((const float4*)bo)[lane];
        acc.x = fmaf(acc.x, inv, b.x); acc.y = fmaf(acc.y, inv, b.y);
        acc.z = fmaf(acc.z, inv, b.z); acc.w = fmaf(acc.w, inv, b.w);
        ((float4*)h)[(size_t)n * 32 + lane] = acc;
    }
    ((float4*)s1)[w * 32 + lane] = acc;
    ((float4*)s2)[w * 32 + lane] =
        make_float4(acc.x * acc.x, acc.y * acc.y, acc.z * acc.z, acc.w * acc.w);
    __syncthreads();
    if (tid < 128) {
        float a = 0.f, b = 0.f;
#pragma unroll
        for (int ww = 0; ww < 8; ww++) { a += s1[ww * 128 + tid]; b += s2[ww * 128 + tid]; }
        atomicAdd(&bns_out[tid], a);
        atomicAdd(&bns_out[128 + tid], b);
    }
}

// --------- attentional pooling + final linear fused (block per graph, 512 thr) ---------
// Four thread-quarters process node strides with ONLINE softmax, then 4-way merge.
__global__ void __launch_bounds__(512) pool_final(const float* __restrict__ gate,
                                                  const float* __restrict__ h,
                                                  const int* __restrict__ gptr,
                                                  const float* __restrict__ bns2,
                                                  const float* __restrict__ g2,
                                                  const float* __restrict__ be2,
                                                  const float* __restrict__ Wf,
                                                  const float* __restrict__ bf,
                                                  float* __restrict__ out) {
    int g = blockIdx.x, tid = threadIdx.x;
    int c = tid & 127, q = tid >> 7;
    __shared__ float sm_m[512], sm_d[512], sm_a[512];
    __shared__ float ps[128];
    int s0 = gptr[g], s1 = gptr[g + 1];
    float mean = bns2[c] * (1.f / (float)kN);
    float var = bns2[128 + c] * (1.f / (float)kN) - mean * mean;
    float sc = rsqrtf(var + 1e-5f) * g2[c];
    float sh = be2[c] - mean * sc;

    float m = -1e30f, den = 0.f, acc = 0.f;
    for (int n = s0 + q; n < s1; n += 4) {
        float gv = gate[(size_t)n * 128 + c];
        float hv = tanhf(fmaf(h[(size_t)n * 128 + c], sc, sh));
        if (gv > m) {
            float corr = __expf(m - gv);
            den *= corr;
            acc *= corr;
            m = gv;
        }
        float e = __expf(gv - m);
        den += e;
        acc = fmaf(e, hv, acc);
    }
    sm_m[tid] = m; sm_d[tid] = den; sm_a[tid] = acc;
    __syncthreads();
    if (tid < 128) {
        float pv = 0.f;
        if (s0 < s1) {
            float M = m;
#pragma unroll
            for (int p = 1; p < 4; p++) M = fmaxf(M, sm_m[tid + p * 128]);
            float D = 0.f, A = 0.f;
#pragma unroll
            for (int p = 0; p < 4; p++) {
                float wq = __expf(sm_m[tid + p * 128] - M);
                D = fmaf(sm_d[tid + p * 128], wq, D);
                A = fmaf(sm_a[tid + p * 128], wq, A);
            }
            pv = A / D;
        }
        ps[c] = pv;
    }
    __syncthreads();
    if (tid < 128) {
        float a = bf[c];
#pragma unroll 8
        for (int k = 0; k < 128; k++) a = fmaf(ps[k], Wf[(size_t)k * 128 + c], a);
        float o = tanhf(a);
        if (c < 64) out[(size_t)g * 64 + c] = o * kPI;
        else        out[(size_t)kG * 64 + (size_t)g * 64 + (c - 64)] = (o + 1.f) * kPI;
    }
}

// ---------------- launch ----------------
extern "C" void kernel_launch(void* const* d_in, const int* in_sizes, int n_in,
                              void* d_out, int out_size) {
    (void)in_sizes; (void)n_in; (void)out_size;
    const float* x    = (const float*)d_in[0];
    const int*   ei   = (const int*)  d_in[1];
    const float* ea   = (const float*)d_in[2];
    const int*   bat  = (const int*)  d_in[3];
    const float* Wl1  = (const float*)d_in[4];
    const float* bl1  = (const float*)d_in[5];
    const float* Wr1  = (const float*)d_in[6];
    const float* br1  = (const float*)d_in[7];
    const float* We1  = (const float*)d_in[8];
    const float* att1 = (const float*)d_in[9];
    const float* bo1  = (const float*)d_in[10];
    const float* Wl2  = (const float*)d_in[11];
    const float* bl2  = (const float*)d_in[12];
    const float* Wr2  = (const float*)d_in[13];
    const float* br2  = (const float*)d_in[14];
    const float* We2  = (const float*)d_in[15];
    const float* att2 = (const float*)d_in[16];
    const float* bo2  = (const float*)d_in[17];
    const float* g1   = (const float*)d_in[18];
    const float* be1  = (const float*)d_in[19];
    const float* g2   = (const float*)d_in[20];
    const float* be2  = (const float*)d_in[21];
    const float* Ag1  = (const float*)d_in[22];
    const float* bg1  = (const float*)d_in[23];
    const float* Ag2  = (const float*)d_in[24];
    const float* bg2  = (const float*)d_in[25];
    const float* Wf   = (const float*)d_in[26];
    const float* bf   = (const float*)d_in[27];
    float* out = (float*)d_out;

    int *deg, *rowptr, *fill, *csr_src, *csr_dst, *csr_eid, *bsums, *gcnt, *gptr;
    float *loopb, *xl, *xr, *h, *ase, *asf, *bns;
    __half* eah;
    uint4* BF;
    cudaGetSymbolAddress((void**)&deg,     g_deg);
    cudaGetSymbolAddress((void**)&rowptr,  g_rowptr);
    cudaGetSymbolAddress((void**)&fill,    g_fill);
    cudaGetSymbolAddress((void**)&csr_src, g_csr_src);
    cudaGetSymbolAddress((void**)&csr_dst, g_csr_dst);
    cudaGetSymbolAddress((void**)&csr_eid, g_csr_eid);
    cudaGetSymbolAddress((void**)&bsums,   g_bsums);
    cudaGetSymbolAddress((void**)&gcnt,    g_gcnt);
    cudaGetSymbolAddress((void**)&gptr,    g_gptr);
    cudaGetSymbolAddress((void**)&loopb,   g_loop);
    cudaGetSymbolAddress((void**)&xl,      g_xl);
    cudaGetSymbolAddress((void**)&xr,      g_xr);
    cudaGetSymbolAddress((void**)&h,       g_h);
    cudaGetSymbolAddress((void**)&ase,     g_ase);
    cudaGetSymbolAddress((void**)&asf,     g_asf);
    cudaGetSymbolAddress((void**)&bns,     g_bns);
    cudaGetSymbolAddress((void**)&eah,     g_eah);
    cudaGetSymbolAddress((void**)&BF,      g_BF);

    cudaFuncSetAttribute(mma_gemm<0, true,  false>, cudaFuncAttributeMaxDynamicSharedMemorySize, SM_TOT);
    cudaFuncSetAttribute(mma_gemm<0, true,  true>,  cudaFuncAttributeMaxDynamicSharedMemorySize, SM_TOT);
    cudaFuncSetAttribute(mma_gemm<2, false, false>, cudaFuncAttributeMaxDynamicSharedMemorySize, SM_TOT);
    cudaFuncSetAttribute(mma_gemm<3, false, false>, cudaFuncAttributeMaxDynamicSharedMemorySize, SM_TOT);
    cudaFuncSetAttribute(mma_gemm<5, false, false>, cudaFuncAttributeMaxDynamicSharedMemorySize, SM_TOT);
    cudaFuncSetAttribute(mma_gemm<6, false, true>,  cudaFuncAttributeMaxDynamicSharedMemorySize, SM_TOT);

    const int* srcp = ei;
    const int* dstp = ei + kE;
    const int gN = (kN + 127) / 128;
    const int gE = (kE + 127) / 128;
    const int nb = (kN + 511) / 512;

    prep_B<<<8, 256>>>(Wl1, Wr1, We1, Wl2, Wr2, We2, Ag1, Ag2, BF);                                   // 0
    zero3<<<(kN + 255) / 256, 256>>>(deg, fill, gcnt, bns, kN);                                       // 1
    hist_kernel<<<(kE + 255) / 256, 256>>>(dstp, deg, kE);                                            // 2
    mma_gemm<0, true, false><<<gN, 512, SM_TOT>>>(x, nullptr, BF + 0 * 4096, BF + 1 * 4096, bl1, br1,
                                                  nullptr, nullptr, nullptr, nullptr, nullptr, nullptr,
                                                  nullptr, nullptr, nullptr, xl, xr, kN);             // 3 <- profile
    hist_kernel<<<(kN + 255) / 256, 256>>>(bat, gcnt, kN);
    scan_block<<<nb, 512>>>(deg, rowptr, bsums, kN);
    scan_sums<<<1, 512>>>(bsums, nb);
    scan_add<<<nb, 512>>>(rowptr, bsums, kN, kE, rowptr + kN);
    gscan<<<1, 256>>>(gcnt, gptr);
    scatter_kernel<<<(kE + 255) / 256, 256>>>(srcp, dstp, rowptr, fill, csr_src, csr_dst, csr_eid, kE);

    // ---- layer 1 ----
    mma_gemm<2, false, false><<<gE, 512, SM_TOT>>>(ea, nullptr, BF + 2 * 4096, nullptr, att1, nullptr,
                                                   xl, xr, csr_src, csr_dst, csr_eid, eah,
                                                   nullptr, nullptr, nullptr, ase, nullptr, kE);
    loopattr_kernel<<<(kN + 7) / 8, 256>>>(eah, rowptr, loopb);
    mma_gemm<3, false, false><<<gN, 512, SM_TOT>>>(loopb, nullptr, BF + 2 * 4096, nullptr, att1, nullptr,
                                                   xl, xr, nullptr, nullptr, nullptr, nullptr,
                                                   nullptr, nullptr, nullptr, asf, nullptr, kN);
    aggregate_kernel<<<(kN + 7) / 8, 256>>>(rowptr, csr_src, ase, asf, xl, bo1, h, bns);

    // ---- layer 2 (BN-1 applied inside the A stage of the dual node GEMM) ----
    mma_gemm<0, true, true><<<gN, 512, SM_TOT>>>(h, nullptr, BF + 3 * 4096, BF + 4 * 4096, bl2, br2,
                                                 nullptr, nullptr, nullptr, nullptr, nullptr, nullptr,
                                                 bns, g1, be1, xl, xr, kN);
    mma_gemm<3, false, false><<<gN, 512, SM_TOT>>>(loopb, nullptr, BF + 5 * 4096, nullptr, att2, nullptr,
                                                   xl, xr, nullptr, nullptr, nullptr, nullptr,
                                                   nullptr, nullptr, nullptr, asf, nullptr, kN);
    mma_gemm<5, false, false><<<gE, 512, SM_TOT>>>(nullptr, eah, BF + 5 * 4096, nullptr, att2, nullptr,
                                                   xl, xr, csr_src, csr_dst, nullptr, nullptr,
                                                   nullptr, nullptr, nullptr, ase, nullptr, kE);
    aggregate_kernel<<<(kN + 7) / 8, 256>>>(rowptr, csr_src, ase, asf, xl, bo2, h, bns + 256);

    // ---- fused gate (BN-2 in A stage) + fused pool/final ----
    mma_gemm<6, false, true><<<gN, 512, SM_TOT>>>(h, nullptr, BF + 6 * 4096, BF + 7 * 4096, bg1, bg2,
                                                  nullptr, nullptr, nullptr, nullptr, nullptr, nullptr,
                                                  bns + 256, g2, be2, xr, nullptr, kN);
    pool_final<<<kG, 512>>>(xr, h, gptr, bns + 256, g2, be2, Wf, bf, out);
}

// round 17
// speedup vs baseline: 1.1447x; 1.0202x over previous
#include <cuda_runtime.h>
#include <cuda_fp16.h>
#include <cstdint>

static constexpr int   kN  = 50000;
static constexpr int   kE  = 600000;
static constexpr int   kC  = 128;
static constexpr int   kG  = 256;
static constexpr float kPI = 3.14159265358979323846f;

// ---------------- scratch (device globals; no allocation allowed) ----------------
__device__ int    g_deg[kN];
__device__ int    g_rowptr[kN + 1];
__device__ int    g_fill[kN];
__device__ int    g_csr_src[kE];
__device__ int    g_csr_dst[kE];
__device__ int    g_csr_eid[kE];
__device__ int    g_bsums[512];
__device__ int    g_gcnt[kG];
__device__ int    g_gptr[kG + 1];
__device__ float  g_loop[kN * kC];
__device__ float  g_xl[kN * kC];
__device__ float  g_xr[kN * kC];
__device__ float  g_h[kN * kC];
__device__ float  g_ase[kE];
__device__ float  g_asf[kN];
__device__ float  g_bns[4 * kC];              // layer1: [0,256), layer2: [256,512)
__device__ __half g_eah[(size_t)kE * kC];     // fp16 edge_attr at CSR positions
// B weights fp16 hi/lo packed per mma fragment: [mat(8)][kk(8)][ntile(16)][lane(32)] uint4
__device__ uint4  g_BF[8 * 4096];

// ---------------- streams/events for fork-join capture (host-side, created once) ----
struct StreamRes {
    cudaStream_t sA = nullptr, sB = nullptr;
    cudaEvent_t eF = nullptr, e1 = nullptr, e2 = nullptr, e3 = nullptr,
                e4 = nullptr, e5 = nullptr, eEnd = nullptr;
    bool ok = false;
    void create() {
        if (ok) return;
        if (cudaStreamCreateWithFlags(&sA, cudaStreamNonBlocking) != cudaSuccess) return;
        if (cudaStreamCreateWithFlags(&sB, cudaStreamNonBlocking) != cudaSuccess) return;
        cudaEventCreateWithFlags(&eF,  cudaEventDisableTiming);
        cudaEventCreateWithFlags(&e1,  cudaEventDisableTiming);
        cudaEventCreateWithFlags(&e2,  cudaEventDisableTiming);
        cudaEventCreateWithFlags(&e3,  cudaEventDisableTiming);
        cudaEventCreateWithFlags(&e4,  cudaEventDisableTiming);
        cudaEventCreateWithFlags(&e5,  cudaEventDisableTiming);
        cudaEventCreateWithFlags(&eEnd, cudaEventDisableTiming);
        ok = true;
    }
    StreamRes() { create(); }
};
static StreamRes g_sr;

// ---------------- small utility kernels ----------------
__global__ void zero3(int* deg, int* fill, int* gcnt, float* bns, int n) {
    int i = blockIdx.x * blockDim.x + threadIdx.x;
    if (i < n) { deg[i] = 0; fill[i] = 0; }
    if (i < kG) gcnt[i] = 0;
    if (i < 4 * kC) bns[i] = 0.f;
}
__global__ void hist_kernel(const int* __restrict__ keys, int* __restrict__ cnt, int n) {
    int i = blockIdx.x * blockDim.x + threadIdx.x;
    if (i < n) atomicAdd(&cnt[keys[i]], 1);
}
__global__ void scan_block(const int* __restrict__ in, int* __restrict__ out,
                           int* __restrict__ bsums, int n) {
    __shared__ int sm[512];
    int tid = threadIdx.x;
    int i = blockIdx.x * 512 + tid;
    int v = (i < n) ? in[i] : 0;
    sm[tid] = v;
    __syncthreads();
#pragma unroll
    for (int off = 1; off < 512; off <<= 1) {
        int t = (tid >= off) ? sm[tid - off] : 0;
        __syncthreads();
        sm[tid] += t;
        __syncthreads();
    }
    if (i < n) out[i] = sm[tid] - v;
    if (tid == 511) bsums[blockIdx.x] = sm[511];
}
__global__ void scan_sums(int* bsums, int nb) {
    __shared__ int sm[512];
    int tid = threadIdx.x;
    int v = (tid < nb) ? bsums[tid] : 0;
    sm[tid] = v;
    __syncthreads();
#pragma unroll
    for (int off = 1; off < 512; off <<= 1) {
        int t = (tid >= off) ? sm[tid - off] : 0;
        __syncthreads();
        sm[tid] += t;
        __syncthreads();
    }
    if (tid < nb) bsums[tid] = sm[tid] - v;
}
__global__ void scan_add(int* out, const int* __restrict__ bsums, int n, int total, int* tail) {
    int i = blockIdx.x * 512 + threadIdx.x;
    if (i < n) out[i] += bsums[blockIdx.x];
    if (blockIdx.x == 0 && threadIdx.x == 0) *tail = total;
}
__global__ void gscan(const int* __restrict__ cnt, int* __restrict__ gptr) {
    __shared__ int sm[256];
    int t = threadIdx.x;
    sm[t] = cnt[t];
    __syncthreads();
#pragma unroll
    for (int off = 1; off < 256; off <<= 1) {
        int u = (t >= off) ? sm[t - off] : 0;
        __syncthreads();
        sm[t] += u;
        __syncthreads();
    }
    if (t == 0) gptr[0] = 0;
    gptr[t + 1] = sm[t];
}
__global__ void scatter_kernel(const int* __restrict__ src, const int* __restrict__ dst,
                               const int* __restrict__ rowptr, int* __restrict__ fill,
                               int* __restrict__ csr_src, int* __restrict__ csr_dst,
                               int* __restrict__ csr_eid, int n) {
    int i = blockIdx.x * blockDim.x + threadIdx.x;
    if (i >= n) return;
    int d = dst[i];
    int pos = rowptr[d] + atomicAdd(&fill[d], 1);
    csr_src[pos] = src[i];
    csr_dst[pos] = d;
    csr_eid[pos] = i;
}

// loop_attr from fp32 edge rows gathered via csr_eid (runs overlapped with edge GEMM)
__global__ void __launch_bounds__(256) loopattr_raw(const float* __restrict__ ea,
                                                    const int* __restrict__ rowptr,
                                                    const int* __restrict__ csr_eid,
                                                    float* __restrict__ loopb) {
    int w = (blockIdx.x * blockDim.x + threadIdx.x) >> 5;
    int lane = threadIdx.x & 31;
    if (w >= kN) return;
    int b0 = rowptr[w], b1 = rowptr[w + 1];
    float4 acc = make_float4(0.f, 0.f, 0.f, 0.f);
    const float4* ea4 = (const float4*)ea;
    for (int j = b0; j < b1; j++) {
        float4 v = ea4[(size_t)csr_eid[j] * 32 + lane];
        acc.x += v.x; acc.y += v.y; acc.z += v.z; acc.w += v.w;
    }
    int dg = b1 - b0;
    float inv = 1.f / (float)(dg > 0 ? dg : 1);
    acc.x *= inv; acc.y *= inv; acc.z *= inv; acc.w *= inv;
    ((float4*)loopb)[(size_t)w * 32 + lane] = acc;
}

__device__ __forceinline__ uint32_t pack2h(float a, float b) {
    __half2 t = __floats2half2_rn(a, b);
    return *reinterpret_cast<uint32_t*>(&t);
}

// ---------------- weight prep: fp16 hi/lo split into mma FRAGMENT order ----------------
__global__ void prep_B(const float* W0, const float* W1, const float* W2, const float* W3,
                       const float* W4, const float* W5, const float* W6, const float* W7,
                       uint4* BF) {
    const float* Ws[8] = {W0, W1, W2, W3, W4, W5, W6, W7};
    const float* W = Ws[blockIdx.x];
    uint4* bf = BF + blockIdx.x * 4096;
    for (int idx = threadIdx.x; idx < 4096; idx += blockDim.x) {
        int lane = idx & 31, nt = (idx >> 5) & 15, kk = idx >> 9;
        int n = nt * 8 + (lane >> 2);
        int k = kk * 16 + (lane & 3) * 2;
        float v00 = W[(size_t)k * 128 + n];
        float v01 = W[(size_t)(k + 1) * 128 + n];
        float v10 = W[(size_t)(k + 8) * 128 + n];
        float v11 = W[(size_t)(k + 9) * 128 + n];
        __half h00 = __float2half_rn(v00), h01 = __float2half_rn(v01);
        __half h10 = __float2half_rn(v10), h11 = __float2half_rn(v11);
        bf[idx] = make_uint4(pack2h(__half2float(h00), __half2float(h01)),
                             pack2h(__half2float(h10), __half2float(h11)),
                             pack2h(v00 - __half2float(h00), v01 - __half2float(h01)),
                             pack2h(v10 - __half2float(h10), v11 - __half2float(h11)));
    }
}

// ============ fp16 2-term tensor-core GEMM (mma.sync), 512 thr, 2 CTA/SM ============
static constexpr int SMS   = 136;
static constexpr int SM_A  = 0;
static constexpr int SM_FB = 34816;
static constexpr int SM_EX = SM_FB + 67584;
static constexpr int SM_RA = SM_EX + 1024;
static constexpr int SM_BN = SM_RA + 512;
static constexpr int SM_TOT = SM_BN + 1024;            // 104960
static constexpr int CSTR  = 132;

__device__ __forceinline__ uint32_t smem_u32(const void* p) {
    uint32_t a;
    asm("{ .reg .u64 t; cvta.to.shared.u64 t, %1; cvt.u32.u64 %0, t; }" : "=r"(a) : "l"(p));
    return a;
}
__device__ __forceinline__ void ldsm4(uint32_t* r, uint32_t addr) {
    asm volatile("ldmatrix.sync.aligned.m8n8.x4.shared.b16 {%0,%1,%2,%3}, [%4];"
                 : "=r"(r[0]), "=r"(r[1]), "=r"(r[2]), "=r"(r[3]) : "r"(addr));
}
__device__ __forceinline__ void mma16816(float* c, const uint32_t* a, uint32_t b0, uint32_t b1) {
    asm volatile("mma.sync.aligned.m16n8k16.row.col.f32.f16.f16.f32 "
                 "{%0,%1,%2,%3}, {%4,%5,%6,%7}, {%8,%9}, {%0,%1,%2,%3};"
                 : "+f"(c[0]), "+f"(c[1]), "+f"(c[2]), "+f"(c[3])
                 : "r"(a[0]), "r"(a[1]), "r"(a[2]), "r"(a[3]), "r"(b0), "r"(b1));
}

// MODE: 0 node(+bias) [DUAL optional], 2 edge score l1 (gather via eid, exports eah),
//       3 self score (s=d=row), 5 edge score l2 (A = eah fp16 direct),
//       6 fused gate: pass0 tanh(A@B+extra)->A-smem, pass1 @B2+extra2 -> out
template <int MODE, bool DUAL, bool BN>
__global__ void __launch_bounds__(512, 2) mma_gemm(const float* __restrict__ A,
                                                   const __half* __restrict__ Ah,
                                                   const uint4* __restrict__ BF,
                                                   const uint4* __restrict__ B2F,
                                                   const float* __restrict__ extra,
                                                   const float* __restrict__ extra2,
                                                   const float* __restrict__ xl,
                                                   const float* __restrict__ xr,
                                                   const int* __restrict__ srcI,
                                                   const int* __restrict__ dstI,
                                                   const int* __restrict__ eid,
                                                   __half* __restrict__ eah_out,
                                                   const float* __restrict__ bn_st,
                                                   const float* __restrict__ bn_g,
                                                   const float* __restrict__ bn_b,
                                                   float* __restrict__ out,
                                                   float* __restrict__ out2, int M) {
    extern __shared__ char smem[];
    const uint32_t sb = smem_u32(smem);
    const int tid = threadIdx.x, w = tid >> 5, lane = tid & 31;
    const int row0 = blockIdx.x * 128;
    float* fbuf = (float*)(smem + SM_FB);
    float* exS = (float*)(smem + SM_EX);
    float* rowacc = (float*)(smem + SM_RA);
    float* bnS = (float*)(smem + SM_BN);

    // ---- A stage ----
    if (MODE == 5) {
        uint2 hv[8];
#pragma unroll
        for (int u = 0; u < 8; u++) {
            int i = tid + u * 512;
            int r = i >> 5, c8 = i & 31;
            int grow = row0 + r;
            hv[u] = (grow < M) ? ((const uint2*)Ah)[(size_t)grow * 32 + c8]
                               : make_uint2(0u, 0u);
        }
        if (tid < 128) exS[tid] = extra[tid];
#pragma unroll
        for (int u = 0; u < 8; u++) {
            int i = tid + u * 512;
            int r = i >> 5, c8 = i & 31;
            *(uint2*)(smem + SM_A + (uint32_t)(r * SMS + c8 * 4) * 2u) = hv[u];
        }
    } else {
        float4 av[8];
#pragma unroll
        for (int u = 0; u < 8; u++) {
            int i = tid + u * 512;
            int r = i >> 5, c4 = (i & 31) << 2;
            int grow = row0 + r;
            av[u] = make_float4(0.f, 0.f, 0.f, 0.f);
            if (grow < M) {
                size_t arow = (MODE == 2) ? (size_t)eid[grow] : (size_t)grow;
                av[u] = *(const float4*)(A + arow * 128 + c4);
            }
        }
        if (tid < 128) exS[tid] = extra[tid];
        if ((DUAL || MODE == 6) && tid >= 128 && tid < 256) exS[tid] = extra2[tid - 128];
        if (BN) {
            if (tid < 128) {
                float mean = bn_st[tid] * (1.f / (float)kN);
                float var = bn_st[128 + tid] * (1.f / (float)kN) - mean * mean;
                float sc = rsqrtf(var + 1e-5f) * bn_g[tid];
                bnS[tid] = sc;
                bnS[128 + tid] = bn_b[tid] - mean * sc;
            }
            __syncthreads();
        }
#pragma unroll
        for (int u = 0; u < 8; u++) {
            int i = tid + u * 512;
            int r = i >> 5, c4 = (i & 31) << 2;
            float4 v = av[u];
            if (BN) {
                v.x = tanhf(fmaf(v.x, bnS[c4 + 0], bnS[128 + c4 + 0]));
                v.y = tanhf(fmaf(v.y, bnS[c4 + 1], bnS[128 + c4 + 1]));
                v.z = tanhf(fmaf(v.z, bnS[c4 + 2], bnS[128 + c4 + 2]));
                v.w = tanhf(fmaf(v.w, bnS[c4 + 3], bnS[128 + c4 + 3]));
            }
            uint2 pk = make_uint2(pack2h(v.x, v.y), pack2h(v.z, v.w));
            *(uint2*)(smem + SM_A + (uint32_t)(r * SMS + c4) * 2u) = pk;
            if (MODE == 2) {
                int grow = row0 + r;
                if (grow < M) ((uint2*)eah_out)[(size_t)grow * 32 + (c4 >> 2)] = pk;
            }
        }
    }
    __syncthreads();

    const int m_base = (w & 3) * 32;
    const int nt0 = (w >> 2) * 4;
    const int n_base = nt0 * 8;
    const int lr = lane & 15, lc = lane >> 4;
    const int tg = lane >> 2, tq = lane & 3;
    const int NPASS = (DUAL || MODE == 6) ? 2 : 1;

#pragma unroll
    for (int pass = 0; pass < NPASS; pass++) {
        const uint4* Bp = pass ? B2F : BF;
        float acc[2][4][4];
#pragma unroll
        for (int mi = 0; mi < 2; mi++)
#pragma unroll
            for (int ni = 0; ni < 4; ni++)
#pragma unroll
                for (int q = 0; q < 4; q++) acc[mi][ni][q] = 0.f;

#pragma unroll
        for (int kk = 0; kk < 8; kk++) {
            int k0 = kk * 16;
            uint4 b[4];
            const uint4* bp = Bp + ((kk * 16 + nt0) * 32 + lane);
#pragma unroll
            for (int ni = 0; ni < 4; ni++) b[ni] = bp[ni * 32];
#pragma unroll
            for (int mi = 0; mi < 2; mi++) {
                uint32_t a[4];
                ldsm4(a, sb + SM_A + (uint32_t)((m_base + mi * 16 + lr) * SMS + k0 + lc * 8) * 2u);
#pragma unroll
                for (int ni = 0; ni < 4; ni++) mma16816(acc[mi][ni], a, b[ni].x, b[ni].y);
#pragma unroll
                for (int ni = 0; ni < 4; ni++) mma16816(acc[mi][ni], a, b[ni].z, b[ni].w);
            }
        }
        __syncthreads();

        if (MODE == 6 && pass == 0) {
#pragma unroll
            for (int mi = 0; mi < 2; mi++) {
                int rlo = m_base + mi * 16 + tg;
#pragma unroll
                for (int ni = 0; ni < 4; ni++) {
                    int c0 = n_base + ni * 8 + 2 * tq;
                    float v0 = tanhf(acc[mi][ni][0] + exS[c0]);
                    float v1 = tanhf(acc[mi][ni][1] + exS[c0 + 1]);
                    float v2 = tanhf(acc[mi][ni][2] + exS[c0]);
                    float v3 = tanhf(acc[mi][ni][3] + exS[c0 + 1]);
                    *(uint32_t*)(smem + SM_A + (uint32_t)(rlo * SMS + c0) * 2u) = pack2h(v0, v1);
                    *(uint32_t*)(smem + SM_A + (uint32_t)((rlo + 8) * SMS + c0) * 2u) = pack2h(v2, v3);
                }
            }
            __syncthreads();
            continue;
        }

        if (MODE == 0 || MODE == 6) {
            const float* ex = exS + (pass ? 128 : 0);
#pragma unroll
            for (int mi = 0; mi < 2; mi++) {
                int rlo = m_base + mi * 16 + tg;
#pragma unroll
                for (int ni = 0; ni < 4; ni++) {
                    int c0 = n_base + ni * 8 + 2 * tq;
                    float v0 = acc[mi][ni][0] + ex[c0];
                    float v1 = acc[mi][ni][1] + ex[c0 + 1];
                    float v2 = acc[mi][ni][2] + ex[c0];
                    float v3 = acc[mi][ni][3] + ex[c0 + 1];
                    *(float2*)(fbuf + rlo * CSTR + c0) = make_float2(v0, v1);
                    *(float2*)(fbuf + (rlo + 8) * CSTR + c0) = make_float2(v2, v3);
                }
            }
            __syncthreads();
            float* o = (DUAL && pass) ? out2 : out;
#pragma unroll
            for (int u = 0; u < 8; u++) {
                int i = tid + u * 512;
                int r = i >> 5, c4 = (i & 31) << 2;
                if (row0 + r < M)
                    *(float4*)(o + (size_t)(row0 + r) * 128 + c4) = *(float4*)(fbuf + r * CSTR + c4);
            }
            if (DUAL && pass == 0) __syncthreads();
        } else {
            if (tid < 128) rowacc[tid] = 0.f;
#pragma unroll
            for (int half = 0; half < 2; half++) {
                int su[4], du[4];
#pragma unroll
                for (int u = 0; u < 4; u++) {
                    int i = tid + (half * 4 + u) * 512;
                    int r = i >> 5;
                    int grow = row0 + r;
                    if (grow >= M) grow = M - 1;
                    su[u] = (MODE == 3) ? grow : srcI[grow];
                    du[u] = (MODE == 3) ? grow : dstI[grow];
                }
                float4 ga[4], gb[4];
#pragma unroll
                for (int u = 0; u < 4; u++) {
                    int i = tid + (half * 4 + u) * 512;
                    int c = i & 31;
                    ga[u] = ((const float4*)xl)[(size_t)su[u] * 32 + c];
                    gb[u] = ((const float4*)xr)[(size_t)du[u] * 32 + c];
                }
#pragma unroll
                for (int u = 0; u < 4; u++) {
                    int i = tid + (half * 4 + u) * 512;
                    int r = i >> 5, c = i & 31;
                    *(float4*)(fbuf + r * CSTR + c * 4) =
                        make_float4(ga[u].x + gb[u].x, ga[u].y + gb[u].y,
                                    ga[u].z + gb[u].z, ga[u].w + gb[u].w);
                }
            }
            __syncthreads();
#pragma unroll
            for (int mi = 0; mi < 2; mi++) {
                int rlo = m_base + mi * 16 + tg;
                int rhi = rlo + 8;
                float p0 = 0.f, p1 = 0.f;
#pragma unroll
                for (int ni = 0; ni < 4; ni++) {
                    int c0 = n_base + ni * 8 + 2 * tq;
                    float e0 = exS[c0], e1 = exS[c0 + 1];
                    float2 flo = *(const float2*)(fbuf + rlo * CSTR + c0);
                    float2 fhi = *(const float2*)(fbuf + rhi * CSTR + c0);
                    float v;
                    v = acc[mi][ni][0] + flo.x;  v = (v > 0.f) ? v : 0.2f * v;  p0 = fmaf(v, e0, p0);
                    v = acc[mi][ni][1] + flo.y;  v = (v > 0.f) ? v : 0.2f * v;  p0 = fmaf(v, e1, p0);
                    v = acc[mi][ni][2] + fhi.x;  v = (v > 0.f) ? v : 0.2f * v;  p1 = fmaf(v, e0, p1);
                    v = acc[mi][ni][3] + fhi.y;  v = (v > 0.f) ? v : 0.2f * v;  p1 = fmaf(v, e1, p1);
                }
                atomicAdd(&rowacc[rlo], p0);
                atomicAdd(&rowacc[rhi], p1);
            }
            __syncthreads();
            if (tid < 128 && row0 + tid < M) out[row0 + tid] = rowacc[tid];
        }
    }
}

// ------- softmax + aggregation (warp per node, CSR) + fused BN partial stats -------
__global__ void __launch_bounds__(256) aggregate_kernel(const int* __restrict__ rowptr,
                                                        const int* __restrict__ csr_src,
                                                        const float* __restrict__ ae,
                                                        const float* __restrict__ as,
                                                        const float* __restrict__ xl,
                                                        const float* __restrict__ bo,
                                                        float* __restrict__ h,
                                                        float* __restrict__ bns_out) {
    __shared__ float s1[8 * 128];
    __shared__ float s2[8 * 128];
    int tid = threadIdx.x, w = tid >> 5, lane = tid & 31;
    int n = (blockIdx.x * blockDim.x + tid) >> 5;
    float4 acc = make_float4(0.f, 0.f, 0.f, 0.f);
    if (n < kN) {
        int b0 = rowptr[n], b1 = rowptr[n + 1];
        float aself = as[n];
        float am = aself;
        for (int j = b0 + lane; j < b1; j += 32) am = fmaxf(am, ae[j]);
#pragma unroll
        for (int off = 16; off; off >>= 1) am = fmaxf(am, __shfl_xor_sync(0xffffffffu, am, off));
        float den = 0.f;
        for (int j = b0 + lane; j < b1; j += 32) den += __expf(ae[j] - am);
#pragma unroll
        for (int off = 16; off; off >>= 1) den += __shfl_xor_sync(0xffffffffu, den, off);
        float wself = __expf(aself - am);
        den += wself;
        float inv = 1.f / den;

        const float4* xl4 = (const float4*)xl;
        int j = b0;
        for (; j + 1 < b1; j += 2) {
            float w0 = __expf(ae[j] - am);
            float w1 = __expf(ae[j + 1] - am);
            int s0i = csr_src[j], s1i = csr_src[j + 1];
            float4 v0 = xl4[(size_t)s0i * 32 + lane];
            float4 v1 = xl4[(size_t)s1i * 32 + lane];
            acc.x = fmaf(w0, v0.x, fmaf(w1, v1.x, acc.x));
            acc.y = fmaf(w0, v0.y, fmaf(w1, v1.y, acc.y));
            acc.z = fmaf(w0, v0.z, fmaf(w1, v1.z, acc.z));
            acc.w = fmaf(w0, v0.w, fmaf(w1, v1.w, acc.w));
        }
        if (j < b1) {
            float w0 = __expf(ae[j] - am);
            float4 v0 = xl4[(size_t)csr_src[j] * 32 + lane];
            acc.x = fmaf(w0, v0.x, acc.x); acc.y = fmaf(w0, v0.y, acc.y);
            acc.z = fmaf(w0, v0.z, acc.z); acc.w = fmaf(w0, v0.w, acc.w);
        }
        {
            float4 v = xl4[(size_t)n * 32 + lane];
            acc.x = fmaf(wself, v.x, acc.x); acc.y = fmaf(wself, v.y, acc.y);
            acc.z = fmaf(wself, v.z, acc.z); acc.w = fmaf(wself, v.w, acc.w);
        }
        float4 b = ((const float4*)bo)[lane];
        acc.x = fmaf(acc.x, inv, b.x); acc.y = fmaf(acc.y, inv, b.y);
        acc.z = fmaf(acc.z, inv, b.z); acc.w = fmaf(acc.w, inv, b.w);
        ((float4*)h)[(size_t)n * 32 + lane] = acc;
    }
    ((float4*)s1)[w * 32 + lane] = acc;
    ((float4*)s2)[w * 32 + lane] =
        make_float4(acc.x * acc.x, acc.y * acc.y, acc.z * acc.z, acc.w * acc.w);
    __syncthreads();
    if (tid < 128) {
        float a = 0.f, b = 0.f;
#pragma unroll
        for (int ww = 0; ww < 8; ww++) { a += s1[ww * 128 + tid]; b += s2[ww * 128 + tid]; }
        atomicAdd(&bns_out[tid], a);
        atomicAdd(&bns_out[128 + tid], b);
    }
}

// --------- attentional pooling + final linear fused (block per graph, 512 thr) ---------
__global__ void __launch_bounds__(512) pool_final(const float* __restrict__ gate,
                                                  const float* __restrict__ h,
                                                  const int* __restrict__ gptr,
                                                  const float* __restrict__ bns2,
                                                  const float* __restrict__ g2,
                                                  const float* __restrict__ be2,
                                                  const float* __restrict__ Wf,
                                                  const float* __restrict__ bf,
                                                  float* __restrict__ out) {
    int g = blockIdx.x, tid = threadIdx.x;
    int c = tid & 127, q = tid >> 7;
    __shared__ float sm_m[512], sm_d[512], sm_a[512];
    __shared__ float ps[128];
    int s0 = gptr[g], s1 = gptr[g + 1];
    float mean = bns2[c] * (1.f / (float)kN);
    float var = bns2[128 + c] * (1.f / (float)kN) - mean * mean;
    float sc = rsqrtf(var + 1e-5f) * g2[c];
    float sh = be2[c] - mean * sc;

    float m = -1e30f, den = 0.f, acc = 0.f;
    for (int n = s0 + q; n < s1; n += 4) {
        float gv = gate[(size_t)n * 128 + c];
        float hv = tanhf(fmaf(h[(size_t)n * 128 + c], sc, sh));
        if (gv > m) {
            float corr = __expf(m - gv);
            den *= corr;
            acc *= corr;
            m = gv;
        }
        float e = __expf(gv - m);
        den += e;
        acc = fmaf(e, hv, acc);
    }
    sm_m[tid] = m; sm_d[tid] = den; sm_a[tid] = acc;
    __syncthreads();
    if (tid < 128) {
        float pv = 0.f;
        if (s0 < s1) {
            float M = m;
#pragma unroll
            for (int p = 1; p < 4; p++) M = fmaxf(M, sm_m[tid + p * 128]);
            float D = 0.f, A = 0.f;
#pragma unroll
            for (int p = 0; p < 4; p++) {
                float wq = __expf(sm_m[tid + p * 128] - M);
                D = fmaf(sm_d[tid + p * 128], wq, D);
                A = fmaf(sm_a[tid + p * 128], wq, A);
            }
            pv = A / D;
        }
        ps[c] = pv;
    }
    __syncthreads();
    if (tid < 128) {
        float a = bf[c];
#pragma unroll 8
        for (int k = 0; k < 128; k++) a = fmaf(ps[k], Wf[(size_t)k * 128 + c], a);
        float o = tanhf(a);
        if (c < 64) out[(size_t)g * 64 + c] = o * kPI;
        else        out[(size_t)kG * 64 + (size_t)g * 64 + (c - 64)] = (o + 1.f) * kPI;
    }
}

// ---------------- launch ----------------
extern "C" void kernel_launch(void* const* d_in, const int* in_sizes, int n_in,
                              void* d_out, int out_size) {
    (void)in_sizes; (void)n_in; (void)out_size;
    const float* x    = (const float*)d_in[0];
    const int*   ei   = (const int*)  d_in[1];
    const float* ea   = (const float*)d_in[2];
    const int*   bat  = (const int*)  d_in[3];
    const float* Wl1  = (const float*)d_in[4];
    const float* bl1  = (const float*)d_in[5];
    const float* Wr1  = (const float*)d_in[6];
    const float* br1  = (const float*)d_in[7];
    const float* We1  = (const float*)d_in[8];
    const float* att1 = (const float*)d_in[9];
    const float* bo1  = (const float*)d_in[10];
    const float* Wl2  = (const float*)d_in[11];
    const float* bl2  = (const float*)d_in[12];
    const float* Wr2  = (const float*)d_in[13];
    const float* br2  = (const float*)d_in[14];
    const float* We2  = (const float*)d_in[15];
    const float* att2 = (const float*)d_in[16];
    const float* bo2  = (const float*)d_in[17];
    const float* g1   = (const float*)d_in[18];
    const float* be1  = (const float*)d_in[19];
    const float* g2   = (const float*)d_in[20];
    const float* be2  = (const float*)d_in[21];
    const float* Ag1  = (const float*)d_in[22];
    const float* bg1  = (const float*)d_in[23];
    const float* Ag2  = (const float*)d_in[24];
    const float* bg2  = (const float*)d_in[25];
    const float* Wf   = (const float*)d_in[26];
    const float* bf   = (const float*)d_in[27];
    float* out = (float*)d_out;

    int *deg, *rowptr, *fill, *csr_src, *csr_dst, *csr_eid, *bsums, *gcnt, *gptr;
    float *loopb, *xl, *xr, *h, *ase, *asf, *bns;
    __half* eah;
    uint4* BF;
    cudaGetSymbolAddress((void**)&deg,     g_deg);
    cudaGetSymbolAddress((void**)&rowptr,  g_rowptr);
    cudaGetSymbolAddress((void**)&fill,    g_fill);
    cudaGetSymbolAddress((void**)&csr_src, g_csr_src);
    cudaGetSymbolAddress((void**)&csr_dst, g_csr_dst);
    cudaGetSymbolAddress((void**)&csr_eid, g_csr_eid);
    cudaGetSymbolAddress((void**)&bsums,   g_bsums);
    cudaGetSymbolAddress((void**)&gcnt,    g_gcnt);
    cudaGetSymbolAddress((void**)&gptr,    g_gptr);
    cudaGetSymbolAddress((void**)&loopb,   g_loop);
    cudaGetSymbolAddress((void**)&xl,      g_xl);
    cudaGetSymbolAddress((void**)&xr,      g_xr);
    cudaGetSymbolAddress((void**)&h,       g_h);
    cudaGetSymbolAddress((void**)&ase,     g_ase);
    cudaGetSymbolAddress((void**)&asf,     g_asf);
    cudaGetSymbolAddress((void**)&bns,     g_bns);
    cudaGetSymbolAddress((void**)&eah,     g_eah);
    cudaGetSymbolAddress((void**)&BF,      g_BF);

    cudaFuncSetAttribute(mma_gemm<0, true,  false>, cudaFuncAttributeMaxDynamicSharedMemorySize, SM_TOT);
    cudaFuncSetAttribute(mma_gemm<0, true,  true>,  cudaFuncAttributeMaxDynamicSharedMemorySize, SM_TOT);
    cudaFuncSetAttribute(mma_gemm<2, false, false>, cudaFuncAttributeMaxDynamicSharedMemorySize, SM_TOT);
    cudaFuncSetAttribute(mma_gemm<3, false, false>, cudaFuncAttributeMaxDynamicSharedMemorySize, SM_TOT);
    cudaFuncSetAttribute(mma_gemm<5, false, false>, cudaFuncAttributeMaxDynamicSharedMemorySize, SM_TOT);
    cudaFuncSetAttribute(mma_gemm<6, false, true>,  cudaFuncAttributeMaxDynamicSharedMemorySize, SM_TOT);

    const int* srcp = ei;
    const int* dstp = ei + kE;
    const int gN = (kN + 127) / 128;
    const int gE = (kE + 127) / 128;
    const int nb = (kN + 511) / 512;

    g_sr.create();   // no-op if static init succeeded
    cudaStream_t sA = g_sr.ok ? g_sr.sA : (cudaStream_t)0;
    cudaStream_t sB = g_sr.ok ? g_sr.sB : (cudaStream_t)0;

    // ---- fork both worker streams from the capture-origin (legacy) stream ----
    if (g_sr.ok) {
        cudaEventRecord(g_sr.eF, (cudaStream_t)0);
        cudaStreamWaitEvent(sA, g_sr.eF, 0);
        cudaStreamWaitEvent(sB, g_sr.eF, 0);
    }

    // ---- sB: CSR build chain ----
    zero3<<<(kN + 255) / 256, 256, 0, sB>>>(deg, fill, gcnt, bns, kN);
    hist_kernel<<<(kE + 255) / 256, 256, 0, sB>>>(dstp, deg, kE);
    hist_kernel<<<(kN + 255) / 256, 256, 0, sB>>>(bat, gcnt, kN);
    scan_block<<<nb, 512, 0, sB>>>(deg, rowptr, bsums, kN);
    scan_sums<<<1, 512, 0, sB>>>(bsums, nb);
    scan_add<<<nb, 512, 0, sB>>>(rowptr, bsums, kN, kE, rowptr + kN);
    gscan<<<1, 256, 0, sB>>>(gcnt, gptr);
    scatter_kernel<<<(kE + 255) / 256, 256, 0, sB>>>(srcp, dstp, rowptr, fill,
                                                     csr_src, csr_dst, csr_eid, kE);
    if (g_sr.ok) cudaEventRecord(g_sr.e1, sB);
    // sB: loop_attr from raw fp32 ea (overlaps edge GEMM L1 on sA)
    loopattr_raw<<<(kN + 7) / 8, 256, 0, sB>>>(ea, rowptr, csr_eid, loopb);

    // ---- sA: weight prep + node GEMM L1 ----
    prep_B<<<8, 256, 0, sA>>>(Wl1, Wr1, We1, Wl2, Wr2, We2, Ag1, Ag2, BF);
    mma_gemm<0, true, false><<<gN, 512, SM_TOT, sA>>>(x, nullptr, BF + 0 * 4096, BF + 1 * 4096,
                                                      bl1, br1, nullptr, nullptr, nullptr, nullptr,
                                                      nullptr, nullptr, nullptr, nullptr, nullptr,
                                                      xl, xr, kN);
    if (g_sr.ok) cudaEventRecord(g_sr.e2, sA);

    // ---- sB: self score L1 (needs xl/xr) ----
    if (g_sr.ok) cudaStreamWaitEvent(sB, g_sr.e2, 0);
    mma_gemm<3, false, false><<<gN, 512, SM_TOT, sB>>>(loopb, nullptr, BF + 2 * 4096, nullptr,
                                                       att1, nullptr, xl, xr, nullptr, nullptr,
                                                       nullptr, nullptr, nullptr, nullptr, nullptr,
                                                       asf, nullptr, kN);
    if (g_sr.ok) cudaEventRecord(g_sr.e3, sB);

    // ---- sA: edge GEMM L1 (needs CSR) ----
    if (g_sr.ok) cudaStreamWaitEvent(sA, g_sr.e1, 0);
    mma_gemm<2, false, false><<<gE, 512, SM_TOT, sA>>>(ea, nullptr, BF + 2 * 4096, nullptr,
                                                       att1, nullptr, xl, xr, csr_src, csr_dst,
                                                       csr_eid, eah, nullptr, nullptr, nullptr,
                                                       ase, nullptr, kE);
    if (g_sr.ok) cudaStreamWaitEvent(sA, g_sr.e3, 0);
    aggregate_kernel<<<(kN + 7) / 8, 256, 0, sA>>>(rowptr, csr_src, ase, asf, xl, bo1, h, bns);

    // ---- layer 2 ----
    mma_gemm<0, true, true><<<gN, 512, SM_TOT, sA>>>(h, nullptr, BF + 3 * 4096, BF + 4 * 4096,
                                                     bl2, br2, nullptr, nullptr, nullptr, nullptr,
                                                     nullptr, nullptr, bns, g1, be1, xl, xr, kN);
    if (g_sr.ok) cudaEventRecord(g_sr.e4, sA);
    // sB: self score L2 (overlaps edge GEMM L2 on sA)
    if (g_sr.ok) cudaStreamWaitEvent(sB, g_sr.e4, 0);
    mma_gemm<3, false, false><<<gN, 512, SM_TOT, sB>>>(loopb, nullptr, BF + 5 * 4096, nullptr,
                                                       att2, nullptr, xl, xr, nullptr, nullptr,
                                                       nullptr, nullptr, nullptr, nullptr, nullptr,
                                                       asf, nullptr, kN);
    if (g_sr.ok) cudaEventRecord(g_sr.e5, sB);
    // sA: edge GEMM L2
    mma_gemm<5, false, false><<<gE, 512, SM_TOT, sA>>>(nullptr, eah, BF + 5 * 4096, nullptr,
                                                       att2, nullptr, xl, xr, csr_src, csr_dst,
                                                       nullptr, nullptr, nullptr, nullptr, nullptr,
                                                       ase, nullptr, kE);
    if (g_sr.ok) cudaStreamWaitEvent(sA, g_sr.e5, 0);
    aggregate_kernel<<<(kN + 7) / 8, 256, 0, sA>>>(rowptr, csr_src, ase, asf, xl, bo2, h, bns + 256);

    // ---- fused gate + pool/final ----
    mma_gemm<6, false, true><<<gN, 512, SM_TOT, sA>>>(h, nullptr, BF + 6 * 4096, BF + 7 * 4096,
                                                      bg1, bg2, nullptr, nullptr, nullptr, nullptr,
                                                      nullptr, nullptr, bns + 256, g2, be2,
                                                      xr, nullptr, kN);
    pool_final<<<kG, 512, 0, sA>>>(xr, h, gptr, bns + 256, g2, be2, Wf, bf, out);

    // ---- join back to the origin stream ----
    if (g_sr.ok) {
        cudaEventRecord(g_sr.eEnd, sA);
        cudaStreamWaitEvent((cudaStream_t)0, g_sr.eEnd, 0);
    }
}